// round 2
// baseline (speedup 1.0000x reference)
#include <cuda_runtime.h>
#include <cstdint>

__device__ float g_l[8 * 256 * 4096];
__device__ float g_t[8 * 128 * 4096];
__device__ float g_lam[8 * 4096 * 256];
__device__ float g_S[256 * 256];
__device__ float g_avg[8 * 256];
__device__ float g_mx[8 * 256];
__device__ float g_sca[8 * 256];
__device__ float g_s2m[8 * 4096];
__device__ float g_s2x[8 * 4096];
__device__ float g_satt[8 * 4096];

__device__ __forceinline__ unsigned long long pk2(float a, float b) {
    unsigned long long r;
    asm("mov.b64 %0, {%1, %2};" : "=l"(r) : "f"(a), "f"(b));
    return r;
}
__device__ __forceinline__ void upk2(unsigned long long v, float& a, float& b) {
    asm("mov.b64 {%0, %1}, %2;" : "=f"(a), "=f"(b) : "l"(v));
}
__device__ __forceinline__ void ffma2(unsigned long long& d, unsigned long long a,
                                      unsigned long long b) {
    asm("fma.rn.f32x2 %0, %1, %2, %0;" : "+l"(d) : "l"(a), "l"(b));
}

// S = I - (Dict^T Dict)/L  (symmetric)
__global__ void compute_S_k(const float* __restrict__ Dict, const float* __restrict__ Lp,
                            float* __restrict__ S) {
    int j = blockIdx.x, t = threadIdx.x;
    float g = 0.f;
#pragma unroll
    for (int c = 0; c < 64; ++c) g += Dict[c * 256 + j] * Dict[c * 256 + t];
    S[j * 256 + t] = (j == t ? 1.f : 0.f) - g / Lp[0];
}

// direct 3x3 conv, pad=1; 256 threads = 256 pixels, 16 out-ch per block (grid.y)
template <int CI, int CO, bool RELU, bool BIAS>
__global__ __launch_bounds__(256) void conv3x3_k(const float* __restrict__ in,
                                                 const float* __restrict__ wt,
                                                 const float* __restrict__ bias,
                                                 float* __restrict__ out) {
    __shared__ __align__(16) float wsh[16 * 64 * 9];
    int tid = threadIdx.x;
    int p = blockIdx.x * 256 + tid;
    int b = p >> 12, hw = p & 4095, h = hw >> 6, wc = hw & 63;
    int coBase = blockIdx.y * 16;
    unsigned long long acc2[8];
#pragma unroll
    for (int j = 0; j < 8; ++j)
        acc2[j] = BIAS ? pk2(bias[coBase + 2 * j], bias[coBase + 2 * j + 1]) : 0ULL;
    const float* inb = in + (size_t)b * CI * 4096;
    for (int cc = 0; cc < CI / 64; ++cc) {
        __syncthreads();
        for (int i = tid; i < 16 * 64 * 9; i += 256) {
            int o = i / 576, r = i - o * 576;
            wsh[r * 16 + o] = wt[(size_t)(coBase + o) * (CI * 9) + cc * 576 + r];
        }
        __syncthreads();
        const float* inc = inb + (size_t)cc * 64 * 4096;
#pragma unroll 1
        for (int ci = 0; ci < 64; ++ci) {
            const float* ip = inc + (size_t)ci * 4096;
#pragma unroll
            for (int kh = 0; kh < 3; ++kh) {
                int hh = h + kh - 1;
                bool rok = (unsigned)hh < 64u;
#pragma unroll
                for (int kw = 0; kw < 3; ++kw) {
                    int ww = wc + kw - 1;
                    float v = (rok && (unsigned)ww < 64u) ? ip[hh * 64 + ww] : 0.f;
                    if (RELU) v = fmaxf(v, 0.f);
                    unsigned long long vv = pk2(v, v);
                    const ulonglong2* wp =
                        (const ulonglong2*)&wsh[(ci * 9 + kh * 3 + kw) * 16];
#pragma unroll
                    for (int q = 0; q < 4; ++q) {
                        ulonglong2 wq = wp[q];
                        ffma2(acc2[2 * q], wq.x, vv);
                        ffma2(acc2[2 * q + 1], wq.y, vv);
                    }
                }
            }
        }
    }
    size_t ob = ((size_t)b * CO + coBase) * 4096 + hw;
#pragma unroll
    for (int j = 0; j < 8; ++j) {
        float v0, v1;
        upk2(acc2[j], v0, v1);
        out[ob + (size_t)(2 * j) * 4096] = v0;
        out[ob + (size_t)(2 * j + 1) * 4096] = v1;
    }
}

// 1x1 conv (relu(t)@w2) + residual add in place; CI=128, 16 co per block
__global__ __launch_bounds__(256) void conv1x1_add_k(const float* __restrict__ tin,
                                                     const float* __restrict__ wt,
                                                     float* __restrict__ lio) {
    __shared__ __align__(16) float wsh[128 * 16];
    int tid = threadIdx.x;
    int p = blockIdx.x * 256 + tid;
    int b = p >> 12, hw = p & 4095;
    int coBase = blockIdx.y * 16;
    for (int i = tid; i < 2048; i += 256) {
        int o = i >> 7, ci = i & 127;
        wsh[ci * 16 + o] = wt[(size_t)(coBase + o) * 128 + ci];
    }
    __syncthreads();
    unsigned long long acc2[8];
    size_t lb = ((size_t)b * 256 + coBase) * 4096 + hw;
#pragma unroll
    for (int j = 0; j < 8; ++j)
        acc2[j] = pk2(lio[lb + (size_t)(2 * j) * 4096],
                      lio[lb + (size_t)(2 * j + 1) * 4096]);
    const float* tb = tin + (size_t)b * 128 * 4096 + hw;
#pragma unroll 1
    for (int ci = 0; ci < 128; ++ci) {
        float v = fmaxf(tb[(size_t)ci * 4096], 0.f);
        unsigned long long vv = pk2(v, v);
        const ulonglong2* wp = (const ulonglong2*)&wsh[ci * 16];
#pragma unroll
        for (int q = 0; q < 4; ++q) {
            ulonglong2 wq = wp[q];
            ffma2(acc2[2 * q], wq.x, vv);
            ffma2(acc2[2 * q + 1], wq.y, vv);
        }
    }
#pragma unroll
    for (int j = 0; j < 8; ++j) {
        float v0, v1;
        upk2(acc2[j], v0, v1);
        lio[lb + (size_t)(2 * j) * 4096] = v0;
        lio[lb + (size_t)(2 * j + 1) * 4096] = v1;
    }
}

__global__ __launch_bounds__(256) void pool_k(const float* __restrict__ l,
                                              float* __restrict__ avg,
                                              float* __restrict__ mx) {
    __shared__ float ss[256], sm[256];
    int bc = blockIdx.x, t = threadIdx.x;
    const float* p = l + (size_t)bc * 4096;
    float s = 0.f, m = -3.4e38f;
    for (int i = t; i < 4096; i += 256) {
        float v = p[i];
        s += v;
        m = fmaxf(m, v);
    }
    ss[t] = s;
    sm[t] = m;
    __syncthreads();
    for (int st = 128; st > 0; st >>= 1) {
        if (t < st) {
            ss[t] += ss[t + st];
            sm[t] = fmaxf(sm[t], sm[t + st]);
        }
        __syncthreads();
    }
    if (t == 0) {
        avg[bc] = ss[0] * (1.f / 4096.f);
        mx[bc] = sm[0];
    }
}

__global__ void camlp_k(const float* __restrict__ avg, const float* __restrict__ mx,
                        const float* __restrict__ w1, const float* __restrict__ w2,
                        float* __restrict__ sca) {
    __shared__ float hsh[128];
    int t = threadIdx.x;
    if (t < 128) {
        int b = t >> 4, j = t & 15;
        float a = 0.f, m = 0.f;
        for (int c = 0; c < 256; ++c) {
            float w = w1[j * 256 + c];
            a += avg[b * 256 + c] * w;
            m += mx[b * 256 + c] * w;
        }
        hsh[b * 16 + j] = fmaxf(a, 0.f) + fmaxf(m, 0.f);
    }
    __syncthreads();
    for (int b = 0; b < 8; ++b) {
        float o = 0.f;
#pragma unroll
        for (int j = 0; j < 16; ++j) o += hsh[b * 16 + j] * w2[t * 16 + j];
        sca[b * 256 + t] = 1.f / (1.f + expf(-o));
    }
}

__global__ __launch_bounds__(256) void chan_k(float* __restrict__ l,
                                              const float* __restrict__ sca,
                                              float* __restrict__ s2m,
                                              float* __restrict__ s2x) {
    int p = blockIdx.x * 256 + threadIdx.x;
    int b = p >> 12, hw = p & 4095;
    size_t base = (size_t)b * 256 * 4096 + hw;
    float s = 0.f, m = -3.4e38f;
#pragma unroll 1
    for (int c = 0; c < 256; ++c) {
        float v = l[base + (size_t)c * 4096] * sca[b * 256 + c];
        l[base + (size_t)c * 4096] = v;
        s += v;
        m = fmaxf(m, v);
    }
    s2m[p] = s * (1.f / 256.f);
    s2x[p] = m;
}

__global__ void sconv_k(const float* __restrict__ s2m, const float* __restrict__ s2x,
                        const float* __restrict__ sw, float* __restrict__ satt) {
    int p = blockIdx.x * 256 + threadIdx.x;
    int b = p >> 12, hw = p & 4095, h = hw >> 6, w = hw & 63;
    float a = 0.f;
#pragma unroll
    for (int kh = 0; kh < 3; ++kh) {
        int hh = h + kh - 1;
        if ((unsigned)hh >= 64u) continue;
#pragma unroll
        for (int kw = 0; kw < 3; ++kw) {
            int ww = w + kw - 1;
            if ((unsigned)ww >= 64u) continue;
            int q = b * 4096 + hh * 64 + ww;
            a += s2m[q] * sw[kh * 3 + kw] + s2x[q] * sw[9 + kh * 3 + kw];
        }
    }
    satt[p] = 1.f / (1.f + expf(-a));
}

// lam NHWC = (l * satt) / L, tiled transpose
__global__ void lamT_k(const float* __restrict__ l, const float* __restrict__ satt,
                       const float* __restrict__ Lp, float* __restrict__ lam) {
    __shared__ float tile[32][33];
    int pb = blockIdx.x * 32, cb = blockIdx.y * 32;
    int tx = threadIdx.x, ty = threadIdx.y;
    int b = pb >> 12, pl = pb & 4095;
#pragma unroll
    for (int k = 0; k < 4; ++k) {
        int c = cb + ty + 8 * k;
        tile[ty + 8 * k][tx] = l[((size_t)b * 256 + c) * 4096 + pl + tx];
    }
    __syncthreads();
    float invL = 1.f / Lp[0];
#pragma unroll
    for (int k = 0; k < 4; ++k) {
        int p2 = pb + ty + 8 * k;
        float sc = satt[p2] * invL;
        lam[(size_t)p2 * 256 + cb + tx] = tile[tx][ty + 8 * k] * sc;
    }
}

// LISTA: 64 pixels/CTA, all iterations in-kernel; thread t = atom column
#define ZTR_OFF 0
#define YL_OFF 17408
#define LAM_OFF (17408 + 16384)
#define XSH_OFF (17408 + 32768)
#define LISTA_SMEM ((17408 + 16384 + 16384 + 64 * 65) * 4)

__global__ __launch_bounds__(256, 1) void lista_k(
    const float* __restrict__ x, const float* __restrict__ Dict,
    const float* __restrict__ Lp, const int* __restrict__ nip,
    const float* __restrict__ lam_g, const float* __restrict__ S,
    float* __restrict__ out_z, float* __restrict__ out_r) {
    extern __shared__ __align__(16) float smem[];
    float* ztr = smem + ZTR_OFF;   // [256][68]
    float* yL = smem + YL_OFF;     // [64][256]
    float* lamS = smem + LAM_OFF;  // [64][256]
    float* xsh = smem + XSH_OFF;   // [64][65]
    int t = threadIdx.x;
    int pbase = blockIdx.x * 64;
    int b = pbase >> 12, pl = pbase & 4095;

    size_t xofs = (size_t)b * 64 * 4096 + pl;
    for (int i = t; i < 4096; i += 256) {
        int c = i >> 6, m = i & 63;
        xsh[m * 65 + c] = x[xofs + (size_t)c * 4096 + m];
    }
    const float* lg = lam_g + (size_t)pbase * 256;
    for (int i = t; i < 16384; i += 256) lamS[i] = lg[i];
    __syncthreads();

    float invL = 1.f / Lp[0];
    int niters = nip[0];

    float acc[64];
#pragma unroll
    for (int m = 0; m < 64; ++m) acc[m] = 0.f;
#pragma unroll 1
    for (int c = 0; c < 64; ++c) {
        float d = Dict[c * 256 + t];
#pragma unroll
        for (int m = 0; m < 64; ++m) acc[m] += xsh[m * 65 + c] * d;
    }
#pragma unroll
    for (int m = 0; m < 64; ++m) {
        float y = acc[m];
        yL[m * 256 + t] = y * invL;
        float lam = lamS[m * 256 + t];
        float mg = fmaxf(fabsf(y) - lam, 0.f);
        float sg = (float)((y > 0.f) - (y < 0.f));
        ztr[t * 68 + m] = sg * mg;
    }
    __syncthreads();

    for (int it = 0; it < niters; ++it) {
        unsigned long long acc2[32];
#pragma unroll
        for (int j = 0; j < 32; ++j)
            acc2[j] = pk2(yL[(2 * j) * 256 + t], yL[(2 * j + 1) * 256 + t]);
        float s_cur = S[t];
#pragma unroll 2
        for (int k = 0; k < 256; ++k) {
            float s_nxt = (k < 255) ? S[(k + 1) * 256 + t] : 0.f;
            unsigned long long ss = pk2(s_cur, s_cur);
            const ulonglong2* zp = (const ulonglong2*)(ztr + k * 68);
#pragma unroll
            for (int i = 0; i < 16; ++i) {
                ulonglong2 q = zp[i];
                ffma2(acc2[2 * i], q.x, ss);
                ffma2(acc2[2 * i + 1], q.y, ss);
            }
            s_cur = s_nxt;
        }
        __syncthreads();
#pragma unroll
        for (int j = 0; j < 32; ++j) {
            float v0, v1;
            upk2(acc2[j], v0, v1);
            int m0 = 2 * j;
            float l0 = lamS[m0 * 256 + t], l1 = lamS[(m0 + 1) * 256 + t];
            float g0 = fmaxf(fabsf(v0) - l0, 0.f);
            float g1 = fmaxf(fabsf(v1) - l1, 0.f);
            float sg0 = (float)((v0 > 0.f) - (v0 < 0.f));
            float sg1 = (float)((v1 > 0.f) - (v1 < 0.f));
            ztr[t * 68 + m0] = sg0 * g0;
            ztr[t * 68 + m0 + 1] = sg1 * g1;
        }
        __syncthreads();
    }

    {   // x_recon = z @ Dict^T
        int c = t & 63, g = t >> 6;
        float r[16];
#pragma unroll
        for (int i = 0; i < 16; ++i) r[i] = 0.f;
#pragma unroll 1
        for (int a = 0; a < 256; ++a) {
            float d = Dict[c * 256 + a];
#pragma unroll
            for (int i = 0; i < 16; ++i) r[i] += ztr[a * 68 + g * 16 + i] * d;
        }
        __syncthreads();
#pragma unroll
        for (int i = 0; i < 16; ++i) xsh[(g * 16 + i) * 65 + c] = r[i];
    }
    __syncthreads();

    size_t zofs = (size_t)b * 256 * 4096 + pl;
    for (int i = t; i < 16384; i += 256) {
        int a = i >> 6, m = i & 63;
        out_z[zofs + (size_t)a * 4096 + m] = ztr[a * 68 + m];
    }
    size_t rofs = (size_t)b * 64 * 4096 + pl;
    for (int i = t; i < 4096; i += 256) {
        int c2 = i >> 6, m = i & 63;
        out_r[rofs + (size_t)c2 * 4096 + m] = xsh[m * 65 + c2];
    }
}

__global__ void copy_k(const float* __restrict__ s, float* __restrict__ d, int n) {
    int i = blockIdx.x * blockDim.x + threadIdx.x;
    if (i < n) d[i] = s[i];
}

extern "C" void kernel_launch(void* const* d_in, const int* in_sizes, int n_in,
                              void* d_out, int out_size) {
    const float* x = (const float*)d_in[0];
    const float* conv_w = (const float*)d_in[1];
    const float* conv_b = (const float*)d_in[2];
    const float* r1w1 = (const float*)d_in[3];
    const float* r1w2 = (const float*)d_in[4];
    const float* r2w1 = (const float*)d_in[5];
    const float* r2w2 = (const float*)d_in[6];
    const float* caw1 = (const float*)d_in[7];
    const float* caw2 = (const float*)d_in[8];
    const float* saw = (const float*)d_in[9];
    const float* Dict = (const float*)d_in[10];
    const float* Lp = (const float*)d_in[11];
    const int* nip = (const int*)d_in[12];
    float* out = (float*)d_out;

    float *l, *tb, *S, *avg, *mx, *sca, *s2m, *s2x, *satt, *lam;
    cudaGetSymbolAddress((void**)&l, g_l);
    cudaGetSymbolAddress((void**)&tb, g_t);
    cudaGetSymbolAddress((void**)&S, g_S);
    cudaGetSymbolAddress((void**)&avg, g_avg);
    cudaGetSymbolAddress((void**)&mx, g_mx);
    cudaGetSymbolAddress((void**)&sca, g_sca);
    cudaGetSymbolAddress((void**)&s2m, g_s2m);
    cudaGetSymbolAddress((void**)&s2x, g_s2x);
    cudaGetSymbolAddress((void**)&satt, g_satt);
    cudaGetSymbolAddress((void**)&lam, g_lam);

    compute_S_k<<<256, 256>>>(Dict, Lp, S);
    conv3x3_k<64, 256, false, true><<<dim3(128, 16), 256>>>(x, conv_w, conv_b, l);
    conv3x3_k<256, 128, true, false><<<dim3(128, 8), 256>>>(l, r1w1, nullptr, tb);
    conv1x1_add_k<<<dim3(128, 16), 256>>>(tb, r1w2, l);
    conv3x3_k<256, 128, true, false><<<dim3(128, 8), 256>>>(l, r2w1, nullptr, tb);
    conv1x1_add_k<<<dim3(128, 16), 256>>>(tb, r2w2, l);
    pool_k<<<2048, 256>>>(l, avg, mx);
    camlp_k<<<1, 256>>>(avg, mx, caw1, caw2, sca);
    chan_k<<<128, 256>>>(l, sca, s2m, s2x);
    sconv_k<<<128, 256>>>(s2m, s2x, saw, satt);
    lamT_k<<<dim3(1024, 8), dim3(32, 8)>>>(l, satt, Lp, lam);

    cudaFuncSetAttribute(lista_k, cudaFuncAttributeMaxDynamicSharedMemorySize,
                         LISTA_SMEM);
    lista_k<<<512, 256, LISTA_SMEM>>>(x, Dict, Lp, nip, lam, S,
                                      out, out + 8 * 256 * 4096);
    copy_k<<<64, 256>>>(Dict, out + 8 * 256 * 4096 + 8 * 64 * 4096, 64 * 256);
}

// round 3
// speedup vs baseline: 1.0613x; 1.0613x over previous
#include <cuda_runtime.h>
#include <cstdint>

__device__ float g_l[8 * 256 * 4096];
__device__ float g_t[8 * 128 * 4096];
__device__ float g_lam[8 * 4096 * 256];
__device__ float g_S[256 * 256];
__device__ float g_avg[8 * 256];
__device__ float g_mx[8 * 256];
__device__ float g_sca[8 * 256];
__device__ float g_s2m[8 * 4096];
__device__ float g_s2x[8 * 4096];
__device__ float g_satt[8 * 4096];

__device__ __forceinline__ unsigned long long pk2(float a, float b) {
    unsigned long long r;
    asm("mov.b64 %0, {%1, %2};" : "=l"(r) : "f"(a), "f"(b));
    return r;
}
__device__ __forceinline__ void upk2(unsigned long long v, float& a, float& b) {
    asm("mov.b64 {%0, %1}, %2;" : "=f"(a), "=f"(b) : "l"(v));
}
__device__ __forceinline__ void ffma2(unsigned long long& d, unsigned long long a,
                                      unsigned long long b) {
    asm("fma.rn.f32x2 %0, %1, %2, %0;" : "+l"(d) : "l"(a), "l"(b));
}

// S = I - (Dict^T Dict)/L  (symmetric)
__global__ void compute_S_k(const float* __restrict__ Dict, const float* __restrict__ Lp,
                            float* __restrict__ S) {
    int j = blockIdx.x, t = threadIdx.x;
    float g = 0.f;
#pragma unroll
    for (int c = 0; c < 64; ++c) g += Dict[c * 256 + j] * Dict[c * 256 + t];
    S[j * 256 + t] = (j == t ? 1.f : 0.f) - g / Lp[0];
}

// direct 3x3 conv, pad=1; 256 threads = 256 pixels, 16 out-ch per block (grid.y)
template <int CI, int CO, bool RELU, bool BIAS>
__global__ __launch_bounds__(256) void conv3x3_k(const float* __restrict__ in,
                                                 const float* __restrict__ wt,
                                                 const float* __restrict__ bias,
                                                 float* __restrict__ out) {
    __shared__ __align__(16) float wsh[16 * 64 * 9];
    int tid = threadIdx.x;
    int p = blockIdx.x * 256 + tid;
    int b = p >> 12, hw = p & 4095, h = hw >> 6, wc = hw & 63;
    int coBase = blockIdx.y * 16;

    int toff[9];
    bool tok[9];
#pragma unroll
    for (int kh = 0; kh < 3; ++kh)
#pragma unroll
        for (int kw = 0; kw < 3; ++kw) {
            int hh = h + kh - 1, ww = wc + kw - 1;
            tok[kh * 3 + kw] = ((unsigned)hh < 64u) && ((unsigned)ww < 64u);
            toff[kh * 3 + kw] = hh * 64 + ww;
        }

    unsigned long long acc2[8];
#pragma unroll
    for (int j = 0; j < 8; ++j)
        acc2[j] = BIAS ? pk2(bias[coBase + 2 * j], bias[coBase + 2 * j + 1]) : 0ULL;

    const float* inb = in + (size_t)b * CI * 4096;
    for (int cc = 0; cc < CI / 64; ++cc) {
        __syncthreads();
        for (int i = tid; i < 16 * 64 * 9; i += 256) {
            int o = i / 576, r = i - o * 576;
            wsh[r * 16 + o] = wt[(size_t)(coBase + o) * (CI * 9) + cc * 576 + r];
        }
        __syncthreads();
        const float* inc = inb + (size_t)cc * 64 * 4096;
#pragma unroll 1
        for (int ci = 0; ci < 64; ++ci) {
            const float* ip = inc + (size_t)ci * 4096;
            float v[9];
#pragma unroll
            for (int tp = 0; tp < 9; ++tp) {
                float u = tok[tp] ? ip[toff[tp]] : 0.f;
                v[tp] = RELU ? fmaxf(u, 0.f) : u;
            }
#pragma unroll
            for (int tp = 0; tp < 9; ++tp) {
                unsigned long long vv = pk2(v[tp], v[tp]);
                const ulonglong2* wp = (const ulonglong2*)&wsh[(ci * 9 + tp) * 16];
#pragma unroll
                for (int q = 0; q < 4; ++q) {
                    ulonglong2 wq = wp[q];
                    ffma2(acc2[2 * q], wq.x, vv);
                    ffma2(acc2[2 * q + 1], wq.y, vv);
                }
            }
        }
    }
    size_t ob = ((size_t)b * CO + coBase) * 4096 + hw;
#pragma unroll
    for (int j = 0; j < 8; ++j) {
        float v0, v1;
        upk2(acc2[j], v0, v1);
        out[ob + (size_t)(2 * j) * 4096] = v0;
        out[ob + (size_t)(2 * j + 1) * 4096] = v1;
    }
}

// 1x1 conv (relu(t)@w2) + residual add in place; CI=128, 16 co per block
__global__ __launch_bounds__(256) void conv1x1_add_k(const float* __restrict__ tin,
                                                     const float* __restrict__ wt,
                                                     float* __restrict__ lio) {
    __shared__ __align__(16) float wsh[128 * 16];
    int tid = threadIdx.x;
    int p = blockIdx.x * 256 + tid;
    int b = p >> 12, hw = p & 4095;
    int coBase = blockIdx.y * 16;
    for (int i = tid; i < 2048; i += 256) {
        int o = i >> 7, ci = i & 127;
        wsh[ci * 16 + o] = wt[(size_t)(coBase + o) * 128 + ci];
    }
    __syncthreads();
    unsigned long long acc2[8];
    size_t lb = ((size_t)b * 256 + coBase) * 4096 + hw;
#pragma unroll
    for (int j = 0; j < 8; ++j)
        acc2[j] = pk2(lio[lb + (size_t)(2 * j) * 4096],
                      lio[lb + (size_t)(2 * j + 1) * 4096]);
    const float* tb = tin + (size_t)b * 128 * 4096 + hw;
#pragma unroll 1
    for (int ci = 0; ci < 128; ci += 8) {
        float v[8];
#pragma unroll
        for (int j = 0; j < 8; ++j) v[j] = fmaxf(tb[(size_t)(ci + j) * 4096], 0.f);
#pragma unroll
        for (int j = 0; j < 8; ++j) {
            unsigned long long vv = pk2(v[j], v[j]);
            const ulonglong2* wp = (const ulonglong2*)&wsh[(ci + j) * 16];
#pragma unroll
            for (int q = 0; q < 4; ++q) {
                ulonglong2 wq = wp[q];
                ffma2(acc2[2 * q], wq.x, vv);
                ffma2(acc2[2 * q + 1], wq.y, vv);
            }
        }
    }
#pragma unroll
    for (int j = 0; j < 8; ++j) {
        float v0, v1;
        upk2(acc2[j], v0, v1);
        lio[lb + (size_t)(2 * j) * 4096] = v0;
        lio[lb + (size_t)(2 * j + 1) * 4096] = v1;
    }
}

__global__ __launch_bounds__(256) void pool_k(const float* __restrict__ l,
                                              float* __restrict__ avg,
                                              float* __restrict__ mx) {
    __shared__ float ss[256], sm[256];
    int bc = blockIdx.x, t = threadIdx.x;
    const float* p = l + (size_t)bc * 4096;
    float s = 0.f, m = -3.4e38f;
    for (int i = t; i < 4096; i += 256) {
        float v = p[i];
        s += v;
        m = fmaxf(m, v);
    }
    ss[t] = s;
    sm[t] = m;
    __syncthreads();
    for (int st = 128; st > 0; st >>= 1) {
        if (t < st) {
            ss[t] += ss[t + st];
            sm[t] = fmaxf(sm[t], sm[t + st]);
        }
        __syncthreads();
    }
    if (t == 0) {
        avg[bc] = ss[0] * (1.f / 4096.f);
        mx[bc] = sm[0];
    }
}

__global__ void camlp_k(const float* __restrict__ avg, const float* __restrict__ mx,
                        const float* __restrict__ w1, const float* __restrict__ w2,
                        float* __restrict__ sca) {
    __shared__ float hsh[128];
    int t = threadIdx.x;
    if (t < 128) {
        int b = t >> 4, j = t & 15;
        float a = 0.f, m = 0.f;
        for (int c = 0; c < 256; ++c) {
            float w = w1[j * 256 + c];
            a += avg[b * 256 + c] * w;
            m += mx[b * 256 + c] * w;
        }
        hsh[b * 16 + j] = fmaxf(a, 0.f) + fmaxf(m, 0.f);
    }
    __syncthreads();
    for (int b = 0; b < 8; ++b) {
        float o = 0.f;
#pragma unroll
        for (int j = 0; j < 16; ++j) o += hsh[b * 16 + j] * w2[t * 16 + j];
        sca[b * 256 + t] = 1.f / (1.f + expf(-o));
    }
}

__global__ __launch_bounds__(256) void chan_k(float* __restrict__ l,
                                              const float* __restrict__ sca,
                                              float* __restrict__ s2m,
                                              float* __restrict__ s2x) {
    int p = blockIdx.x * 256 + threadIdx.x;
    int b = p >> 12, hw = p & 4095;
    size_t base = (size_t)b * 256 * 4096 + hw;
    float s = 0.f, m = -3.4e38f;
#pragma unroll 1
    for (int c = 0; c < 256; c += 8) {
        float v[8];
#pragma unroll
        for (int j = 0; j < 8; ++j)
            v[j] = l[base + (size_t)(c + j) * 4096] * sca[b * 256 + c + j];
#pragma unroll
        for (int j = 0; j < 8; ++j) {
            l[base + (size_t)(c + j) * 4096] = v[j];
            s += v[j];
            m = fmaxf(m, v[j]);
        }
    }
    s2m[p] = s * (1.f / 256.f);
    s2x[p] = m;
}

__global__ void sconv_k(const float* __restrict__ s2m, const float* __restrict__ s2x,
                        const float* __restrict__ sw, float* __restrict__ satt) {
    int p = blockIdx.x * 256 + threadIdx.x;
    int b = p >> 12, hw = p & 4095, h = hw >> 6, w = hw & 63;
    float a = 0.f;
#pragma unroll
    for (int kh = 0; kh < 3; ++kh) {
        int hh = h + kh - 1;
        if ((unsigned)hh >= 64u) continue;
#pragma unroll
        for (int kw = 0; kw < 3; ++kw) {
            int ww = w + kw - 1;
            if ((unsigned)ww >= 64u) continue;
            int q = b * 4096 + hh * 64 + ww;
            a += s2m[q] * sw[kh * 3 + kw] + s2x[q] * sw[9 + kh * 3 + kw];
        }
    }
    satt[p] = 1.f / (1.f + expf(-a));
}

// lam NHWC = (l * satt) / L, tiled transpose
__global__ void lamT_k(const float* __restrict__ l, const float* __restrict__ satt,
                       const float* __restrict__ Lp, float* __restrict__ lam) {
    __shared__ float tile[32][33];
    int pb = blockIdx.x * 32, cb = blockIdx.y * 32;
    int tx = threadIdx.x, ty = threadIdx.y;
    int b = pb >> 12, pl = pb & 4095;
#pragma unroll
    for (int k = 0; k < 4; ++k) {
        int c = cb + ty + 8 * k;
        tile[ty + 8 * k][tx] = l[((size_t)b * 256 + c) * 4096 + pl + tx];
    }
    __syncthreads();
    float invL = 1.f / Lp[0];
#pragma unroll
    for (int k = 0; k < 4; ++k) {
        int p2 = pb + ty + 8 * k;
        float sc = satt[p2] * invL;
        lam[(size_t)p2 * 256 + cb + tx] = tile[tx][ty + 8 * k] * sc;
    }
}

// LISTA: 64 pixels/CTA, 512 threads: thread = (atom, half); all iters in-kernel.
#define ZTR_OFF 0
#define YL_OFF 17408
#define LAM_OFF (17408 + 16384)
#define XSH_OFF (17408 + 32768)
#define LISTA_SMEM ((17408 + 16384 + 16384 + 64 * 65) * 4)

__global__ __launch_bounds__(512, 1) void lista_k(
    const float* __restrict__ x, const float* __restrict__ Dict,
    const float* __restrict__ Lp, const int* __restrict__ nip,
    const float* __restrict__ lam_g, const float* __restrict__ S,
    float* __restrict__ out_z, float* __restrict__ out_r) {
    extern __shared__ __align__(16) float smem[];
    float* ztr = smem + ZTR_OFF;   // [256][68]
    float* yL = smem + YL_OFF;     // [64][256]
    float* lamS = smem + LAM_OFF;  // [64][256]
    float* xsh = smem + XSH_OFF;   // [64][65]
    int t = threadIdx.x;
    int atom = t & 255, half = t >> 8, mb = half * 32;
    int pbase = blockIdx.x * 64;
    int b = pbase >> 12, pl = pbase & 4095;

    size_t xofs = (size_t)b * 64 * 4096 + pl;
    for (int i = t; i < 4096; i += 512) {
        int c = i >> 6, m = i & 63;
        xsh[m * 65 + c] = x[xofs + (size_t)c * 4096 + m];
    }
    const float* lg = lam_g + (size_t)pbase * 256;
    for (int i = t; i < 16384; i += 512) lamS[i] = lg[i];
    __syncthreads();

    float invL = 1.f / Lp[0];
    int niters = nip[0];

    // y = x @ Dict
    float acc[32];
#pragma unroll
    for (int m = 0; m < 32; ++m) acc[m] = 0.f;
#pragma unroll 1
    for (int c = 0; c < 64; ++c) {
        float d = Dict[c * 256 + atom];
#pragma unroll
        for (int m = 0; m < 32; ++m) acc[m] += xsh[(mb + m) * 65 + c] * d;
    }
#pragma unroll
    for (int m = 0; m < 32; ++m) {
        float y = acc[m];
        yL[(mb + m) * 256 + atom] = y * invL;
        float lam = lamS[(mb + m) * 256 + atom];
        float mg = fmaxf(fabsf(y) - lam, 0.f);
        float sg = (float)((y > 0.f) - (y < 0.f));
        ztr[atom * 68 + mb + m] = sg * mg;
    }
    __syncthreads();

    for (int it = 0; it < niters; ++it) {
        unsigned long long acc2[16];
#pragma unroll
        for (int j = 0; j < 16; ++j)
            acc2[j] = pk2(yL[(mb + 2 * j) * 256 + atom],
                          yL[(mb + 2 * j + 1) * 256 + atom]);
        float sreg[8];
#pragma unroll
        for (int j = 0; j < 8; ++j) sreg[j] = S[j * 256 + atom];
#pragma unroll 1
        for (int k0 = 0; k0 < 256; k0 += 8) {
            float snxt[8];
#pragma unroll
            for (int j = 0; j < 8; ++j)
                snxt[j] = (k0 + 8 < 256) ? S[(k0 + 8 + j) * 256 + atom] : 0.f;
#pragma unroll
            for (int j = 0; j < 8; ++j) {
                unsigned long long ss = pk2(sreg[j], sreg[j]);
                const ulonglong2* zp = (const ulonglong2*)(ztr + (k0 + j) * 68 + mb);
#pragma unroll
                for (int i = 0; i < 8; ++i) {
                    ulonglong2 q = zp[i];
                    ffma2(acc2[2 * i], q.x, ss);
                    ffma2(acc2[2 * i + 1], q.y, ss);
                }
            }
#pragma unroll
            for (int j = 0; j < 8; ++j) sreg[j] = snxt[j];
        }
        __syncthreads();
#pragma unroll
        for (int j = 0; j < 16; ++j) {
            float v0, v1;
            upk2(acc2[j], v0, v1);
            int m0 = mb + 2 * j;
            float l0 = lamS[m0 * 256 + atom], l1 = lamS[(m0 + 1) * 256 + atom];
            float g0 = fmaxf(fabsf(v0) - l0, 0.f);
            float g1 = fmaxf(fabsf(v1) - l1, 0.f);
            float sg0 = (float)((v0 > 0.f) - (v0 < 0.f));
            float sg1 = (float)((v1 > 0.f) - (v1 < 0.f));
            ztr[atom * 68 + m0] = sg0 * g0;
            ztr[atom * 68 + m0 + 1] = sg1 * g1;
        }
        __syncthreads();
    }

    // stage Dict transposed into free yL region: dsh[a*65 + c]
    {
        float* dsh = yL;  // 256*65 = 16640 floats <= 32768 (yL+lamS region)
        for (int i = t; i < 16384; i += 512) {
            int c = i >> 8, a = i & 255;
            dsh[a * 65 + c] = Dict[i];
        }
        __syncthreads();
        // x_recon = z @ Dict^T : thread -> (c = t&63, pixel group g = t>>6)
        int c = t & 63, g = t >> 6;
        float r[8];
#pragma unroll
        for (int i = 0; i < 8; ++i) r[i] = 0.f;
#pragma unroll 2
        for (int a = 0; a < 256; ++a) {
            float d = dsh[a * 65 + c];
#pragma unroll
            for (int i = 0; i < 8; ++i) r[i] += ztr[a * 68 + g * 8 + i] * d;
        }
        __syncthreads();
#pragma unroll
        for (int i = 0; i < 8; ++i) xsh[(g * 8 + i) * 65 + c] = r[i];
    }
    __syncthreads();

    size_t zofs = (size_t)b * 256 * 4096 + pl;
    for (int i = t; i < 16384; i += 512) {
        int a = i >> 6, m = i & 63;
        out_z[zofs + (size_t)a * 4096 + m] = ztr[a * 68 + m];
    }
    size_t rofs = (size_t)b * 64 * 4096 + pl;
    for (int i = t; i < 4096; i += 512) {
        int c2 = i >> 6, m = i & 63;
        out_r[rofs + (size_t)c2 * 4096 + m] = xsh[m * 65 + c2];
    }
}

__global__ void copy_k(const float* __restrict__ s, float* __restrict__ d, int n) {
    int i = blockIdx.x * blockDim.x + threadIdx.x;
    if (i < n) d[i] = s[i];
}

extern "C" void kernel_launch(void* const* d_in, const int* in_sizes, int n_in,
                              void* d_out, int out_size) {
    const float* x = (const float*)d_in[0];
    const float* conv_w = (const float*)d_in[1];
    const float* conv_b = (const float*)d_in[2];
    const float* r1w1 = (const float*)d_in[3];
    const float* r1w2 = (const float*)d_in[4];
    const float* r2w1 = (const float*)d_in[5];
    const float* r2w2 = (const float*)d_in[6];
    const float* caw1 = (const float*)d_in[7];
    const float* caw2 = (const float*)d_in[8];
    const float* saw = (const float*)d_in[9];
    const float* Dict = (const float*)d_in[10];
    const float* Lp = (const float*)d_in[11];
    const int* nip = (const int*)d_in[12];
    float* out = (float*)d_out;

    float *l, *tb, *S, *avg, *mx, *sca, *s2m, *s2x, *satt, *lam;
    cudaGetSymbolAddress((void**)&l, g_l);
    cudaGetSymbolAddress((void**)&tb, g_t);
    cudaGetSymbolAddress((void**)&S, g_S);
    cudaGetSymbolAddress((void**)&avg, g_avg);
    cudaGetSymbolAddress((void**)&mx, g_mx);
    cudaGetSymbolAddress((void**)&sca, g_sca);
    cudaGetSymbolAddress((void**)&s2m, g_s2m);
    cudaGetSymbolAddress((void**)&s2x, g_s2x);
    cudaGetSymbolAddress((void**)&satt, g_satt);
    cudaGetSymbolAddress((void**)&lam, g_lam);

    compute_S_k<<<256, 256>>>(Dict, Lp, S);
    conv3x3_k<64, 256, false, true><<<dim3(128, 16), 256>>>(x, conv_w, conv_b, l);
    conv3x3_k<256, 128, true, false><<<dim3(128, 8), 256>>>(l, r1w1, nullptr, tb);
    conv1x1_add_k<<<dim3(128, 16), 256>>>(tb, r1w2, l);
    conv3x3_k<256, 128, true, false><<<dim3(128, 8), 256>>>(l, r2w1, nullptr, tb);
    conv1x1_add_k<<<dim3(128, 16), 256>>>(tb, r2w2, l);
    pool_k<<<2048, 256>>>(l, avg, mx);
    camlp_k<<<1, 256>>>(avg, mx, caw1, caw2, sca);
    chan_k<<<128, 256>>>(l, sca, s2m, s2x);
    sconv_k<<<128, 256>>>(s2m, s2x, saw, satt);
    lamT_k<<<dim3(1024, 8), dim3(32, 8)>>>(l, satt, Lp, lam);

    cudaFuncSetAttribute(lista_k, cudaFuncAttributeMaxDynamicSharedMemorySize,
                         LISTA_SMEM);
    lista_k<<<512, 512, LISTA_SMEM>>>(x, Dict, Lp, nip, lam, S,
                                      out, out + 8 * 256 * 4096);
    copy_k<<<64, 256>>>(Dict, out + 8 * 256 * 4096 + 8 * 64 * 4096, 64 * 256);
}

// round 4
// speedup vs baseline: 1.0614x; 1.0001x over previous
#include <cuda_runtime.h>
#include <cstdint>

__device__ float g_l[8 * 256 * 4096];
__device__ float g_t[8 * 128 * 4096];
__device__ float g_lam[8 * 4096 * 256];
__device__ float g_S[256 * 256];
__device__ float g_avg[8 * 256];
__device__ float g_mx[8 * 256];
__device__ float g_sca[8 * 256];
__device__ float g_s2m[8 * 4096];
__device__ float g_s2x[8 * 4096];
__device__ float g_satt[8 * 4096];

__device__ __forceinline__ unsigned long long pk2(float a, float b) {
    unsigned long long r;
    asm("mov.b64 %0, {%1, %2};" : "=l"(r) : "f"(a), "f"(b));
    return r;
}
__device__ __forceinline__ void upk2(unsigned long long v, float& a, float& b) {
    asm("mov.b64 {%0, %1}, %2;" : "=f"(a), "=f"(b) : "l"(v));
}
__device__ __forceinline__ void ffma2(unsigned long long& d, unsigned long long a,
                                      unsigned long long b) {
    asm("fma.rn.f32x2 %0, %1, %2, %0;" : "+l"(d) : "l"(a), "l"(b));
}

// S = I - (Dict^T Dict)/L  (symmetric)
__global__ void compute_S_k(const float* __restrict__ Dict, const float* __restrict__ Lp,
                            float* __restrict__ S) {
    int j = blockIdx.x, t = threadIdx.x;
    float g = 0.f;
#pragma unroll
    for (int c = 0; c < 64; ++c) g += Dict[c * 256 + j] * Dict[c * 256 + t];
    S[j * 256 + t] = (j == t ? 1.f : 0.f) - g / Lp[0];
}

// direct 3x3 conv, pad=1; 256 threads = 256 pixels, 16 out-ch per block (grid.y)
template <int CI, int CO, bool RELU, bool BIAS>
__global__ __launch_bounds__(256) void conv3x3_k(const float* __restrict__ in,
                                                 const float* __restrict__ wt,
                                                 const float* __restrict__ bias,
                                                 float* __restrict__ out) {
    __shared__ __align__(16) float wsh[16 * 64 * 9];
    int tid = threadIdx.x;
    int p = blockIdx.x * 256 + tid;
    int b = p >> 12, hw = p & 4095, h = hw >> 6, wc = hw & 63;
    int coBase = blockIdx.y * 16;

    int toff[9];
    bool tok[9];
#pragma unroll
    for (int kh = 0; kh < 3; ++kh)
#pragma unroll
        for (int kw = 0; kw < 3; ++kw) {
            int hh = h + kh - 1, ww = wc + kw - 1;
            tok[kh * 3 + kw] = ((unsigned)hh < 64u) && ((unsigned)ww < 64u);
            toff[kh * 3 + kw] = hh * 64 + ww;
        }

    unsigned long long acc2[8];
#pragma unroll
    for (int j = 0; j < 8; ++j)
        acc2[j] = BIAS ? pk2(bias[coBase + 2 * j], bias[coBase + 2 * j + 1]) : 0ULL;

    const float* inb = in + (size_t)b * CI * 4096;
    for (int cc = 0; cc < CI / 64; ++cc) {
        __syncthreads();
        for (int i = tid; i < 16 * 64 * 9; i += 256) {
            int o = i / 576, r = i - o * 576;
            wsh[r * 16 + o] = wt[(size_t)(coBase + o) * (CI * 9) + cc * 576 + r];
        }
        __syncthreads();
        const float* inc = inb + (size_t)cc * 64 * 4096;
#pragma unroll 1
        for (int ci = 0; ci < 64; ++ci) {
            const float* ip = inc + (size_t)ci * 4096;
            float v[9];
#pragma unroll
            for (int tp = 0; tp < 9; ++tp) {
                float u = tok[tp] ? ip[toff[tp]] : 0.f;
                v[tp] = RELU ? fmaxf(u, 0.f) : u;
            }
#pragma unroll
            for (int tp = 0; tp < 9; ++tp) {
                unsigned long long vv = pk2(v[tp], v[tp]);
                const ulonglong2* wp = (const ulonglong2*)&wsh[(ci * 9 + tp) * 16];
#pragma unroll
                for (int q = 0; q < 4; ++q) {
                    ulonglong2 wq = wp[q];
                    ffma2(acc2[2 * q], wq.x, vv);
                    ffma2(acc2[2 * q + 1], wq.y, vv);
                }
            }
        }
    }
    size_t ob = ((size_t)b * CO + coBase) * 4096 + hw;
#pragma unroll
    for (int j = 0; j < 8; ++j) {
        float v0, v1;
        upk2(acc2[j], v0, v1);
        out[ob + (size_t)(2 * j) * 4096] = v0;
        out[ob + (size_t)(2 * j + 1) * 4096] = v1;
    }
}

// 1x1 conv (relu(t)@w2) + residual add in place; CI=128, 16 co per block
__global__ __launch_bounds__(256) void conv1x1_add_k(const float* __restrict__ tin,
                                                     const float* __restrict__ wt,
                                                     float* __restrict__ lio) {
    __shared__ __align__(16) float wsh[128 * 16];
    int tid = threadIdx.x;
    int p = blockIdx.x * 256 + tid;
    int b = p >> 12, hw = p & 4095;
    int coBase = blockIdx.y * 16;
    for (int i = tid; i < 2048; i += 256) {
        int o = i >> 7, ci = i & 127;
        wsh[ci * 16 + o] = wt[(size_t)(coBase + o) * 128 + ci];
    }
    __syncthreads();
    unsigned long long acc2[8];
    size_t lb = ((size_t)b * 256 + coBase) * 4096 + hw;
#pragma unroll
    for (int j = 0; j < 8; ++j)
        acc2[j] = pk2(lio[lb + (size_t)(2 * j) * 4096],
                      lio[lb + (size_t)(2 * j + 1) * 4096]);
    const float* tb = tin + (size_t)b * 128 * 4096 + hw;
#pragma unroll 1
    for (int ci = 0; ci < 128; ci += 8) {
        float v[8];
#pragma unroll
        for (int j = 0; j < 8; ++j) v[j] = fmaxf(tb[(size_t)(ci + j) * 4096], 0.f);
#pragma unroll
        for (int j = 0; j < 8; ++j) {
            unsigned long long vv = pk2(v[j], v[j]);
            const ulonglong2* wp = (const ulonglong2*)&wsh[(ci + j) * 16];
#pragma unroll
            for (int q = 0; q < 4; ++q) {
                ulonglong2 wq = wp[q];
                ffma2(acc2[2 * q], wq.x, vv);
                ffma2(acc2[2 * q + 1], wq.y, vv);
            }
        }
    }
#pragma unroll
    for (int j = 0; j < 8; ++j) {
        float v0, v1;
        upk2(acc2[j], v0, v1);
        lio[lb + (size_t)(2 * j) * 4096] = v0;
        lio[lb + (size_t)(2 * j + 1) * 4096] = v1;
    }
}

__global__ __launch_bounds__(256) void pool_k(const float* __restrict__ l,
                                              float* __restrict__ avg,
                                              float* __restrict__ mx) {
    __shared__ float ss[256], sm[256];
    int bc = blockIdx.x, t = threadIdx.x;
    const float* p = l + (size_t)bc * 4096;
    float s = 0.f, m = -3.4e38f;
    for (int i = t; i < 4096; i += 256) {
        float v = p[i];
        s += v;
        m = fmaxf(m, v);
    }
    ss[t] = s;
    sm[t] = m;
    __syncthreads();
    for (int st = 128; st > 0; st >>= 1) {
        if (t < st) {
            ss[t] += ss[t + st];
            sm[t] = fmaxf(sm[t], sm[t + st]);
        }
        __syncthreads();
    }
    if (t == 0) {
        avg[bc] = ss[0] * (1.f / 4096.f);
        mx[bc] = sm[0];
    }
}

__global__ void camlp_k(const float* __restrict__ avg, const float* __restrict__ mx,
                        const float* __restrict__ w1, const float* __restrict__ w2,
                        float* __restrict__ sca) {
    __shared__ float hsh[128];
    int t = threadIdx.x;
    if (t < 128) {
        int b = t >> 4, j = t & 15;
        float a = 0.f, m = 0.f;
        for (int c = 0; c < 256; ++c) {
            float w = w1[j * 256 + c];
            a += avg[b * 256 + c] * w;
            m += mx[b * 256 + c] * w;
        }
        hsh[b * 16 + j] = fmaxf(a, 0.f) + fmaxf(m, 0.f);
    }
    __syncthreads();
    for (int b = 0; b < 8; ++b) {
        float o = 0.f;
#pragma unroll
        for (int j = 0; j < 16; ++j) o += hsh[b * 16 + j] * w2[t * 16 + j];
        sca[b * 256 + t] = 1.f / (1.f + expf(-o));
    }
}

__global__ __launch_bounds__(256) void chan_k(float* __restrict__ l,
                                              const float* __restrict__ sca,
                                              float* __restrict__ s2m,
                                              float* __restrict__ s2x) {
    int p = blockIdx.x * 256 + threadIdx.x;
    int b = p >> 12, hw = p & 4095;
    size_t base = (size_t)b * 256 * 4096 + hw;
    float s = 0.f, m = -3.4e38f;
#pragma unroll 1
    for (int c = 0; c < 256; c += 8) {
        float v[8];
#pragma unroll
        for (int j = 0; j < 8; ++j)
            v[j] = l[base + (size_t)(c + j) * 4096] * sca[b * 256 + c + j];
#pragma unroll
        for (int j = 0; j < 8; ++j) {
            l[base + (size_t)(c + j) * 4096] = v[j];
            s += v[j];
            m = fmaxf(m, v[j]);
        }
    }
    s2m[p] = s * (1.f / 256.f);
    s2x[p] = m;
}

__global__ void sconv_k(const float* __restrict__ s2m, const float* __restrict__ s2x,
                        const float* __restrict__ sw, float* __restrict__ satt) {
    int p = blockIdx.x * 256 + threadIdx.x;
    int b = p >> 12, hw = p & 4095, h = hw >> 6, w = hw & 63;
    float a = 0.f;
#pragma unroll
    for (int kh = 0; kh < 3; ++kh) {
        int hh = h + kh - 1;
        if ((unsigned)hh >= 64u) continue;
#pragma unroll
        for (int kw = 0; kw < 3; ++kw) {
            int ww = w + kw - 1;
            if ((unsigned)ww >= 64u) continue;
            int q = b * 4096 + hh * 64 + ww;
            a += s2m[q] * sw[kh * 3 + kw] + s2x[q] * sw[9 + kh * 3 + kw];
        }
    }
    satt[p] = 1.f / (1.f + expf(-a));
}

// lam NHWC = (l * satt) / L, tiled transpose
__global__ void lamT_k(const float* __restrict__ l, const float* __restrict__ satt,
                       const float* __restrict__ Lp, float* __restrict__ lam) {
    __shared__ float tile[32][33];
    int pb = blockIdx.x * 32, cb = blockIdx.y * 32;
    int tx = threadIdx.x, ty = threadIdx.y;
    int b = pb >> 12, pl = pb & 4095;
#pragma unroll
    for (int k = 0; k < 4; ++k) {
        int c = cb + ty + 8 * k;
        tile[ty + 8 * k][tx] = l[((size_t)b * 256 + c) * 4096 + pl + tx];
    }
    __syncthreads();
    float invL = 1.f / Lp[0];
#pragma unroll
    for (int k = 0; k < 4; ++k) {
        int p2 = pb + ty + 8 * k;
        float sc = satt[p2] * invL;
        lam[(size_t)p2 * 256 + cb + tx] = tile[tx][ty + 8 * k] * sc;
    }
}

// LISTA: 64 pixels/CTA, 512 threads: thread = (atom, half); all iters in-kernel.
#define ZTR_OFF 0
#define YL_OFF 17408
#define LAM_OFF (17408 + 16384)
#define XSH_OFF (17408 + 32768)
#define LISTA_SMEM ((17408 + 16384 + 16384 + 64 * 65) * 4)

__global__ __launch_bounds__(512, 1) void lista_k(
    const float* __restrict__ x, const float* __restrict__ Dict,
    const float* __restrict__ Lp, const int* __restrict__ nip,
    const float* __restrict__ lam_g, const float* __restrict__ S,
    float* __restrict__ out_z, float* __restrict__ out_r) {
    extern __shared__ __align__(16) float smem[];
    float* ztr = smem + ZTR_OFF;   // [256][68]
    float* yL = smem + YL_OFF;     // [64][256]
    float* lamS = smem + LAM_OFF;  // [64][256]
    float* xsh = smem + XSH_OFF;   // [64][65]
    int t = threadIdx.x;
    int atom = t & 255, half = t >> 8, mb = half * 32;
    int pbase = blockIdx.x * 64;
    int b = pbase >> 12, pl = pbase & 4095;

    size_t xofs = (size_t)b * 64 * 4096 + pl;
    for (int i = t; i < 4096; i += 512) {
        int c = i >> 6, m = i & 63;
        xsh[m * 65 + c] = x[xofs + (size_t)c * 4096 + m];
    }
    const float* lg = lam_g + (size_t)pbase * 256;
    for (int i = t; i < 16384; i += 512) lamS[i] = lg[i];
    __syncthreads();

    float invL = 1.f / Lp[0];
    int niters = nip[0];

    // y = x @ Dict
    float acc[32];
#pragma unroll
    for (int m = 0; m < 32; ++m) acc[m] = 0.f;
#pragma unroll 1
    for (int c = 0; c < 64; ++c) {
        float d = Dict[c * 256 + atom];
#pragma unroll
        for (int m = 0; m < 32; ++m) acc[m] += xsh[(mb + m) * 65 + c] * d;
    }
#pragma unroll
    for (int m = 0; m < 32; ++m) {
        float y = acc[m];
        yL[(mb + m) * 256 + atom] = y * invL;
        float lam = lamS[(mb + m) * 256 + atom];
        float mg = fmaxf(fabsf(y) - lam, 0.f);
        float sg = (float)((y > 0.f) - (y < 0.f));
        ztr[atom * 68 + mb + m] = sg * mg;
    }
    __syncthreads();

    for (int it = 0; it < niters; ++it) {
        unsigned long long acc2[16];
#pragma unroll
        for (int j = 0; j < 16; ++j)
            acc2[j] = pk2(yL[(mb + 2 * j) * 256 + atom],
                          yL[(mb + 2 * j + 1) * 256 + atom]);
        float sreg[8];
#pragma unroll
        for (int j = 0; j < 8; ++j) sreg[j] = S[j * 256 + atom];
#pragma unroll 1
        for (int k0 = 0; k0 < 256; k0 += 8) {
            float snxt[8];
#pragma unroll
            for (int j = 0; j < 8; ++j)
                snxt[j] = (k0 + 8 < 256) ? S[(k0 + 8 + j) * 256 + atom] : 0.f;
#pragma unroll
            for (int j = 0; j < 8; ++j) {
                unsigned long long ss = pk2(sreg[j], sreg[j]);
                const ulonglong2* zp = (const ulonglong2*)(ztr + (k0 + j) * 68 + mb);
#pragma unroll
                for (int i = 0; i < 8; ++i) {
                    ulonglong2 q = zp[i];
                    ffma2(acc2[2 * i], q.x, ss);
                    ffma2(acc2[2 * i + 1], q.y, ss);
                }
            }
#pragma unroll
            for (int j = 0; j < 8; ++j) sreg[j] = snxt[j];
        }
        __syncthreads();
#pragma unroll
        for (int j = 0; j < 16; ++j) {
            float v0, v1;
            upk2(acc2[j], v0, v1);
            int m0 = mb + 2 * j;
            float l0 = lamS[m0 * 256 + atom], l1 = lamS[(m0 + 1) * 256 + atom];
            float g0 = fmaxf(fabsf(v0) - l0, 0.f);
            float g1 = fmaxf(fabsf(v1) - l1, 0.f);
            float sg0 = (float)((v0 > 0.f) - (v0 < 0.f));
            float sg1 = (float)((v1 > 0.f) - (v1 < 0.f));
            ztr[atom * 68 + m0] = sg0 * g0;
            ztr[atom * 68 + m0 + 1] = sg1 * g1;
        }
        __syncthreads();
    }

    // stage Dict transposed into free yL region: dsh[a*65 + c]
    {
        float* dsh = yL;  // 256*65 = 16640 floats <= 32768 (yL+lamS region)
        for (int i = t; i < 16384; i += 512) {
            int c = i >> 8, a = i & 255;
            dsh[a * 65 + c] = Dict[i];
        }
        __syncthreads();
        // x_recon = z @ Dict^T : thread -> (c = t&63, pixel group g = t>>6)
        int c = t & 63, g = t >> 6;
        float r[8];
#pragma unroll
        for (int i = 0; i < 8; ++i) r[i] = 0.f;
#pragma unroll 2
        for (int a = 0; a < 256; ++a) {
            float d = dsh[a * 65 + c];
#pragma unroll
            for (int i = 0; i < 8; ++i) r[i] += ztr[a * 68 + g * 8 + i] * d;
        }
        __syncthreads();
#pragma unroll
        for (int i = 0; i < 8; ++i) xsh[(g * 8 + i) * 65 + c] = r[i];
    }
    __syncthreads();

    size_t zofs = (size_t)b * 256 * 4096 + pl;
    for (int i = t; i < 16384; i += 512) {
        int a = i >> 6, m = i & 63;
        out_z[zofs + (size_t)a * 4096 + m] = ztr[a * 68 + m];
    }
    size_t rofs = (size_t)b * 64 * 4096 + pl;
    for (int i = t; i < 4096; i += 512) {
        int c2 = i >> 6, m = i & 63;
        out_r[rofs + (size_t)c2 * 4096 + m] = xsh[m * 65 + c2];
    }
}

__global__ void copy_k(const float* __restrict__ s, float* __restrict__ d, int n) {
    int i = blockIdx.x * blockDim.x + threadIdx.x;
    if (i < n) d[i] = s[i];
}

extern "C" void kernel_launch(void* const* d_in, const int* in_sizes, int n_in,
                              void* d_out, int out_size) {
    const float* x = (const float*)d_in[0];
    const float* conv_w = (const float*)d_in[1];
    const float* conv_b = (const float*)d_in[2];
    const float* r1w1 = (const float*)d_in[3];
    const float* r1w2 = (const float*)d_in[4];
    const float* r2w1 = (const float*)d_in[5];
    const float* r2w2 = (const float*)d_in[6];
    const float* caw1 = (const float*)d_in[7];
    const float* caw2 = (const float*)d_in[8];
    const float* saw = (const float*)d_in[9];
    const float* Dict = (const float*)d_in[10];
    const float* Lp = (const float*)d_in[11];
    const int* nip = (const int*)d_in[12];
    float* out = (float*)d_out;

    float *l, *tb, *S, *avg, *mx, *sca, *s2m, *s2x, *satt, *lam;
    cudaGetSymbolAddress((void**)&l, g_l);
    cudaGetSymbolAddress((void**)&tb, g_t);
    cudaGetSymbolAddress((void**)&S, g_S);
    cudaGetSymbolAddress((void**)&avg, g_avg);
    cudaGetSymbolAddress((void**)&mx, g_mx);
    cudaGetSymbolAddress((void**)&sca, g_sca);
    cudaGetSymbolAddress((void**)&s2m, g_s2m);
    cudaGetSymbolAddress((void**)&s2x, g_s2x);
    cudaGetSymbolAddress((void**)&satt, g_satt);
    cudaGetSymbolAddress((void**)&lam, g_lam);

    compute_S_k<<<256, 256>>>(Dict, Lp, S);
    conv3x3_k<64, 256, false, true><<<dim3(128, 16), 256>>>(x, conv_w, conv_b, l);
    conv3x3_k<256, 128, true, false><<<dim3(128, 8), 256>>>(l, r1w1, nullptr, tb);
    conv1x1_add_k<<<dim3(128, 16), 256>>>(tb, r1w2, l);
    conv3x3_k<256, 128, true, false><<<dim3(128, 8), 256>>>(l, r2w1, nullptr, tb);
    conv1x1_add_k<<<dim3(128, 16), 256>>>(tb, r2w2, l);
    pool_k<<<2048, 256>>>(l, avg, mx);
    camlp_k<<<1, 256>>>(avg, mx, caw1, caw2, sca);
    chan_k<<<128, 256>>>(l, sca, s2m, s2x);
    sconv_k<<<128, 256>>>(s2m, s2x, saw, satt);
    lamT_k<<<dim3(1024, 8), dim3(32, 8)>>>(l, satt, Lp, lam);

    cudaFuncSetAttribute(lista_k, cudaFuncAttributeMaxDynamicSharedMemorySize,
                         LISTA_SMEM);
    lista_k<<<512, 512, LISTA_SMEM>>>(x, Dict, Lp, nip, lam, S,
                                      out, out + 8 * 256 * 4096);
    copy_k<<<64, 256>>>(Dict, out + 8 * 256 * 4096 + 8 * 64 * 4096, 64 * 256);
}

// round 5
// speedup vs baseline: 1.0670x; 1.0053x over previous
#include <cuda_runtime.h>
#include <cstdint>

__device__ float g_l[8 * 256 * 4096];
__device__ float g_t[8 * 128 * 4096];
__device__ float g_lam[8 * 4096 * 256];
__device__ float g_S[256 * 256];
__device__ float g_avg[8 * 256];
__device__ float g_mx[8 * 256];
__device__ float g_sca[8 * 256];
__device__ float g_s2m[8 * 4096];
__device__ float g_s2x[8 * 4096];
__device__ float g_satt[8 * 4096];

__device__ __forceinline__ unsigned long long pk2(float a, float b) {
    unsigned long long r;
    asm("mov.b64 %0, {%1, %2};" : "=l"(r) : "f"(a), "f"(b));
    return r;
}
__device__ __forceinline__ void upk2(unsigned long long v, float& a, float& b) {
    asm("mov.b64 {%0, %1}, %2;" : "=f"(a), "=f"(b) : "l"(v));
}
__device__ __forceinline__ void ffma2(unsigned long long& d, unsigned long long a,
                                      unsigned long long b) {
    asm("fma.rn.f32x2 %0, %1, %2, %0;" : "+l"(d) : "l"(a), "l"(b));
}

// S = I - (Dict^T Dict)/L  (symmetric)
__global__ void compute_S_k(const float* __restrict__ Dict, const float* __restrict__ Lp,
                            float* __restrict__ S) {
    int j = blockIdx.x, t = threadIdx.x;
    float g = 0.f;
#pragma unroll
    for (int c = 0; c < 64; ++c) g += Dict[c * 256 + j] * Dict[c * 256 + t];
    S[j * 256 + t] = (j == t ? 1.f : 0.f) - g / Lp[0];
}

// direct 3x3 conv, pad=1; 256 threads x 2 pixels, 16 out-ch per block (grid.y)
template <int CI, int CO, bool RELU, bool BIAS>
__global__ __launch_bounds__(256) void conv3x3_k(const float* __restrict__ in,
                                                 const float* __restrict__ wt,
                                                 const float* __restrict__ bias,
                                                 float* __restrict__ out) {
    __shared__ __align__(16) float wsh[16 * 64 * 9];
    int tid = threadIdx.x;
    int p0 = blockIdx.x * 512 + 2 * tid;            // even pixel; pair in same row
    int b = p0 >> 12, hw = p0 & 4095, h = hw >> 6, wc = hw & 63;
    int coBase = blockIdx.y * 16;

    bool rowok[3], colok[4];
#pragma unroll
    for (int kh = 0; kh < 3; ++kh) rowok[kh] = ((unsigned)(h + kh - 1) < 64u);
#pragma unroll
    for (int q = 0; q < 4; ++q) colok[q] = ((unsigned)(wc + q - 1) < 64u);

    unsigned long long acc2[16];  // [co-pair q][pixel px]
#pragma unroll
    for (int q = 0; q < 8; ++q) {
        unsigned long long bi =
            BIAS ? pk2(bias[coBase + 2 * q], bias[coBase + 2 * q + 1]) : 0ULL;
        acc2[2 * q] = bi;
        acc2[2 * q + 1] = bi;
    }

    const float* inb = in + (size_t)b * CI * 4096;
    for (int cc = 0; cc < CI / 64; ++cc) {
        __syncthreads();
        for (int i = tid; i < 16 * 64 * 9; i += 256) {
            int o = i / 576, r = i - o * 576;
            wsh[r * 16 + o] = wt[(size_t)(coBase + o) * (CI * 9) + cc * 576 + r];
        }
        __syncthreads();
        const float* inc = inb + (size_t)cc * 64 * 4096;
#pragma unroll 1
        for (int ci = 0; ci < 64; ++ci) {
            const float* ip = inc + (size_t)ci * 4096;
            float rv[3][4];
#pragma unroll
            for (int kh = 0; kh < 3; ++kh) {
                int rbase = (h + kh - 1) * 64 + wc - 1;
#pragma unroll
                for (int q = 0; q < 4; ++q) {
                    float u = (rowok[kh] && colok[q]) ? ip[rbase + q] : 0.f;
                    rv[kh][q] = RELU ? fmaxf(u, 0.f) : u;
                }
            }
#pragma unroll
            for (int kh = 0; kh < 3; ++kh)
#pragma unroll
                for (int kw = 0; kw < 3; ++kw) {
                    unsigned long long v0 = pk2(rv[kh][kw], rv[kh][kw]);
                    unsigned long long v1 = pk2(rv[kh][kw + 1], rv[kh][kw + 1]);
                    const ulonglong2* wp =
                        (const ulonglong2*)&wsh[(ci * 9 + kh * 3 + kw) * 16];
#pragma unroll
                    for (int q = 0; q < 4; ++q) {
                        ulonglong2 wq = wp[q];
                        ffma2(acc2[4 * q], wq.x, v0);
                        ffma2(acc2[4 * q + 1], wq.x, v1);
                        ffma2(acc2[4 * q + 2], wq.y, v0);
                        ffma2(acc2[4 * q + 3], wq.y, v1);
                    }
                }
        }
    }
    size_t ob = ((size_t)b * CO + coBase) * 4096 + hw;
#pragma unroll
    for (int q = 0; q < 8; ++q) {
        float a0, a1, b0_, b1_;
        upk2(acc2[2 * q], a0, b0_);      // pixel0: co 2q, 2q+1
        upk2(acc2[2 * q + 1], a1, b1_);  // pixel1
        out[ob + (size_t)(2 * q) * 4096] = a0;
        out[ob + (size_t)(2 * q) * 4096 + 1] = a1;
        out[ob + (size_t)(2 * q + 1) * 4096] = b0_;
        out[ob + (size_t)(2 * q + 1) * 4096 + 1] = b1_;
    }
}

// 1x1 conv (relu(t)@w2) + residual add; CI=128, 16 co per block, 2 px/thread
__global__ __launch_bounds__(256) void conv1x1_add_k(const float* __restrict__ tin,
                                                     const float* __restrict__ wt,
                                                     float* __restrict__ lio) {
    __shared__ __align__(16) float wsh[128 * 16];
    int tid = threadIdx.x;
    int p0 = blockIdx.x * 512 + 2 * tid;
    int b = p0 >> 12, hw = p0 & 4095;
    int coBase = blockIdx.y * 16;
    for (int i = tid; i < 2048; i += 256) {
        int o = i >> 7, ci = i & 127;
        wsh[ci * 16 + o] = wt[(size_t)(coBase + o) * 128 + ci];
    }
    __syncthreads();
    unsigned long long acc2[16];
    size_t lb = ((size_t)b * 256 + coBase) * 4096 + hw;
#pragma unroll
    for (int q = 0; q < 8; ++q) {
        float2 v = *(const float2*)&lio[lb + (size_t)(2 * q) * 4096];
        float2 u = *(const float2*)&lio[lb + (size_t)(2 * q + 1) * 4096];
        acc2[2 * q] = pk2(v.x, u.x);      // pixel0: (co 2q, co 2q+1)
        acc2[2 * q + 1] = pk2(v.y, u.y);  // pixel1
    }
    const float* tb = tin + (size_t)b * 128 * 4096 + hw;
#pragma unroll 1
    for (int ci = 0; ci < 128; ci += 8) {
        float2 v[8];
#pragma unroll
        for (int j = 0; j < 8; ++j) {
            float2 u = *(const float2*)&tb[(size_t)(ci + j) * 4096];
            v[j].x = fmaxf(u.x, 0.f);
            v[j].y = fmaxf(u.y, 0.f);
        }
#pragma unroll
        for (int j = 0; j < 8; ++j) {
            unsigned long long v0 = pk2(v[j].x, v[j].x);
            unsigned long long v1 = pk2(v[j].y, v[j].y);
            const ulonglong2* wp = (const ulonglong2*)&wsh[(ci + j) * 16];
#pragma unroll
            for (int q = 0; q < 4; ++q) {
                ulonglong2 wq = wp[q];
                ffma2(acc2[4 * q], wq.x, v0);
                ffma2(acc2[4 * q + 1], wq.x, v1);
                ffma2(acc2[4 * q + 2], wq.y, v0);
                ffma2(acc2[4 * q + 3], wq.y, v1);
            }
        }
    }
#pragma unroll
    for (int q = 0; q < 8; ++q) {
        float a0, a1, b0_, b1_;
        upk2(acc2[2 * q], a0, b0_);
        upk2(acc2[2 * q + 1], a1, b1_);
        float2 o0 = {a0, a1}, o1 = {b0_, b1_};
        *(float2*)&lio[lb + (size_t)(2 * q) * 4096] = o0;
        *(float2*)&lio[lb + (size_t)(2 * q + 1) * 4096] = o1;
    }
}

__global__ __launch_bounds__(256) void pool_k(const float* __restrict__ l,
                                              float* __restrict__ avg,
                                              float* __restrict__ mx) {
    __shared__ float ss[256], sm[256];
    int bc = blockIdx.x, t = threadIdx.x;
    const float4* p = (const float4*)(l + (size_t)bc * 4096);
    float s = 0.f, m = -3.4e38f;
    for (int i = t; i < 1024; i += 256) {
        float4 v = p[i];
        s += v.x + v.y + v.z + v.w;
        m = fmaxf(m, fmaxf(fmaxf(v.x, v.y), fmaxf(v.z, v.w)));
    }
    ss[t] = s;
    sm[t] = m;
    __syncthreads();
    for (int st = 128; st > 0; st >>= 1) {
        if (t < st) {
            ss[t] += ss[t + st];
            sm[t] = fmaxf(sm[t], sm[t + st]);
        }
        __syncthreads();
    }
    if (t == 0) {
        avg[bc] = ss[0] * (1.f / 4096.f);
        mx[bc] = sm[0];
    }
}

__global__ void camlp_k(const float* __restrict__ avg, const float* __restrict__ mx,
                        const float* __restrict__ w1, const float* __restrict__ w2,
                        float* __restrict__ sca) {
    __shared__ float hsh[128];
    int t = threadIdx.x;
    if (t < 128) {
        int b = t >> 4, j = t & 15;
        float a = 0.f, m = 0.f;
        for (int c = 0; c < 256; ++c) {
            float w = w1[j * 256 + c];
            a += avg[b * 256 + c] * w;
            m += mx[b * 256 + c] * w;
        }
        hsh[b * 16 + j] = fmaxf(a, 0.f) + fmaxf(m, 0.f);
    }
    __syncthreads();
    for (int b = 0; b < 8; ++b) {
        float o = 0.f;
#pragma unroll
        for (int j = 0; j < 16; ++j) o += hsh[b * 16 + j] * w2[t * 16 + j];
        sca[b * 256 + t] = 1.f / (1.f + expf(-o));
    }
}

__global__ __launch_bounds__(256) void chan_k(float* __restrict__ l,
                                              const float* __restrict__ sca,
                                              float* __restrict__ s2m,
                                              float* __restrict__ s2x) {
    int tid = threadIdx.x;
    int p0 = blockIdx.x * 512 + 2 * tid;
    int b = p0 >> 12, hw = p0 & 4095;
    size_t base = (size_t)b * 256 * 4096 + hw;
    float s0 = 0.f, s1 = 0.f, m0 = -3.4e38f, m1 = -3.4e38f;
#pragma unroll 1
    for (int c = 0; c < 256; c += 8) {
        float2 v[8];
#pragma unroll
        for (int j = 0; j < 8; ++j) {
            float2 u = *(float2*)&l[base + (size_t)(c + j) * 4096];
            float sc = sca[b * 256 + c + j];
            v[j].x = u.x * sc;
            v[j].y = u.y * sc;
        }
#pragma unroll
        for (int j = 0; j < 8; ++j) {
            *(float2*)&l[base + (size_t)(c + j) * 4096] = v[j];
            s0 += v[j].x;
            s1 += v[j].y;
            m0 = fmaxf(m0, v[j].x);
            m1 = fmaxf(m1, v[j].y);
        }
    }
    s2m[p0] = s0 * (1.f / 256.f);
    s2m[p0 + 1] = s1 * (1.f / 256.f);
    s2x[p0] = m0;
    s2x[p0 + 1] = m1;
}

__global__ void sconv_k(const float* __restrict__ s2m, const float* __restrict__ s2x,
                        const float* __restrict__ sw, float* __restrict__ satt) {
    int p = blockIdx.x * 256 + threadIdx.x;
    int b = p >> 12, hw = p & 4095, h = hw >> 6, w = hw & 63;
    float a = 0.f;
#pragma unroll
    for (int kh = 0; kh < 3; ++kh) {
        int hh = h + kh - 1;
        if ((unsigned)hh >= 64u) continue;
#pragma unroll
        for (int kw = 0; kw < 3; ++kw) {
            int ww = w + kw - 1;
            if ((unsigned)ww >= 64u) continue;
            int q = b * 4096 + hh * 64 + ww;
            a += s2m[q] * sw[kh * 3 + kw] + s2x[q] * sw[9 + kh * 3 + kw];
        }
    }
    satt[p] = 1.f / (1.f + expf(-a));
}

// lam NHWC = (l * satt) / L, tiled transpose
__global__ void lamT_k(const float* __restrict__ l, const float* __restrict__ satt,
                       const float* __restrict__ Lp, float* __restrict__ lam) {
    __shared__ float tile[32][33];
    int pb = blockIdx.x * 32, cb = blockIdx.y * 32;
    int tx = threadIdx.x, ty = threadIdx.y;
    int b = pb >> 12, pl = pb & 4095;
#pragma unroll
    for (int k = 0; k < 4; ++k) {
        int c = cb + ty + 8 * k;
        tile[ty + 8 * k][tx] = l[((size_t)b * 256 + c) * 4096 + pl + tx];
    }
    __syncthreads();
    float invL = 1.f / Lp[0];
#pragma unroll
    for (int k = 0; k < 4; ++k) {
        int p2 = pb + ty + 8 * k;
        float sc = satt[p2] * invL;
        lam[(size_t)p2 * 256 + cb + tx] = tile[tx][ty + 8 * k] * sc;
    }
}

// LISTA: 64 pixels/CTA, 512 threads = (atom, half). yL/lam in registers.
#define ZTR_OFF 0
#define XSH_OFF 17408
#define DSH_OFF (17408 + 4160)
#define LISTA_SMEM ((17408 + 4160 + 16640) * 4)

__global__ __launch_bounds__(512, 1) void lista_k(
    const float* __restrict__ x, const float* __restrict__ Dict,
    const float* __restrict__ Lp, const int* __restrict__ nip,
    const float* __restrict__ lam_g, const float* __restrict__ S,
    float* __restrict__ out_z, float* __restrict__ out_r) {
    extern __shared__ __align__(16) float smem[];
    float* ztr = smem + ZTR_OFF;  // [256][68] k-major z
    float* xsh = smem + XSH_OFF;  // [64][65]
    float* dsh = smem + DSH_OFF;  // [256][65] Dict^T staged
    int t = threadIdx.x;
    int atom = t & 255, half = t >> 8, mb = half * 32;
    int pbase = blockIdx.x * 64;
    int b = pbase >> 12, pl = pbase & 4095;

    size_t xofs = (size_t)b * 64 * 4096 + pl;
    for (int i = t; i < 4096; i += 512) {
        int c = i >> 6, m = i & 63;
        xsh[m * 65 + c] = x[xofs + (size_t)c * 4096 + m];
    }
    __syncthreads();

    float invL = 1.f / Lp[0];
    int niters = nip[0];

    // per-thread private lambda (32 values, registers)
    float lamreg[32];
    {
        const float* lg = lam_g + ((size_t)(pbase + mb)) * 256 + atom;
#pragma unroll
        for (int m = 0; m < 32; ++m) lamreg[m] = lg[(size_t)m * 256];
    }

    // y = x @ Dict ; keep yL packed in registers, write z0 to ztr
    unsigned long long ylpk[16];
    {
        float acc[32];
#pragma unroll
        for (int m = 0; m < 32; ++m) acc[m] = 0.f;
#pragma unroll 1
        for (int c = 0; c < 64; ++c) {
            float d = Dict[c * 256 + atom];
#pragma unroll
            for (int m = 0; m < 32; ++m) acc[m] += xsh[(mb + m) * 65 + c] * d;
        }
#pragma unroll
        for (int j = 0; j < 16; ++j) {
            float y0 = acc[2 * j], y1 = acc[2 * j + 1];
            ylpk[j] = pk2(y0 * invL, y1 * invL);
            float g0 = fmaxf(fabsf(y0) - lamreg[2 * j], 0.f);
            float g1 = fmaxf(fabsf(y1) - lamreg[2 * j + 1], 0.f);
            float z0 = ((y0 > 0.f) ? g0 : -g0);
            float z1 = ((y1 > 0.f) ? g1 : -g1);
            *(unsigned long long*)&ztr[atom * 68 + mb + 2 * j] = pk2(z0, z1);
        }
    }
    __syncthreads();

    for (int it = 0; it < niters; ++it) {
        unsigned long long acc2[16];
#pragma unroll
        for (int j = 0; j < 16; ++j) acc2[j] = ylpk[j];
        float sreg[4];
#pragma unroll
        for (int j = 0; j < 4; ++j) sreg[j] = S[j * 256 + atom];
#pragma unroll 1
        for (int k0 = 0; k0 < 256; k0 += 4) {
            float snxt[4];
#pragma unroll
            for (int j = 0; j < 4; ++j)
                snxt[j] = (k0 + 4 < 256) ? S[(k0 + 4 + j) * 256 + atom] : 0.f;
#pragma unroll
            for (int j = 0; j < 4; ++j) {
                unsigned long long ss = pk2(sreg[j], sreg[j]);
                const ulonglong2* zp = (const ulonglong2*)(ztr + (k0 + j) * 68 + mb);
#pragma unroll
                for (int i = 0; i < 8; ++i) {
                    ulonglong2 q = zp[i];
                    ffma2(acc2[2 * i], q.x, ss);
                    ffma2(acc2[2 * i + 1], q.y, ss);
                }
            }
#pragma unroll
            for (int j = 0; j < 4; ++j) sreg[j] = snxt[j];
        }
        __syncthreads();
#pragma unroll
        for (int j = 0; j < 16; ++j) {
            float v0, v1;
            upk2(acc2[j], v0, v1);
            float g0 = fmaxf(fabsf(v0) - lamreg[2 * j], 0.f);
            float g1 = fmaxf(fabsf(v1) - lamreg[2 * j + 1], 0.f);
            float z0 = ((v0 > 0.f) ? g0 : -g0);
            float z1 = ((v1 > 0.f) ? g1 : -g1);
            *(unsigned long long*)&ztr[atom * 68 + mb + 2 * j] = pk2(z0, z1);
        }
        __syncthreads();
    }

    // stage Dict^T: dsh[a*65 + c]
    for (int i = t; i < 16384; i += 512) {
        int c = i >> 8, a = i & 255;
        dsh[a * 65 + c] = Dict[i];
    }
    __syncthreads();
    {
        // x_recon = z @ Dict^T : thread -> (c = t&63, pixel group g = t>>6)
        int c = t & 63, g = t >> 6;
        float r[8];
#pragma unroll
        for (int i = 0; i < 8; ++i) r[i] = 0.f;
#pragma unroll 2
        for (int a = 0; a < 256; ++a) {
            float d = dsh[a * 65 + c];
#pragma unroll
            for (int i = 0; i < 8; ++i) r[i] += ztr[a * 68 + g * 8 + i] * d;
        }
        __syncthreads();
#pragma unroll
        for (int i = 0; i < 8; ++i) xsh[(g * 8 + i) * 65 + c] = r[i];
    }
    __syncthreads();

    size_t zofs = (size_t)b * 256 * 4096 + pl;
    for (int i = t; i < 16384; i += 512) {
        int a = i >> 6, m = i & 63;
        out_z[zofs + (size_t)a * 4096 + m] = ztr[a * 68 + m];
    }
    size_t rofs = (size_t)b * 64 * 4096 + pl;
    for (int i = t; i < 4096; i += 512) {
        int c2 = i >> 6, m = i & 63;
        out_r[rofs + (size_t)c2 * 4096 + m] = xsh[m * 65 + c2];
    }
}

__global__ void copy_k(const float* __restrict__ s, float* __restrict__ d, int n) {
    int i = blockIdx.x * blockDim.x + threadIdx.x;
    if (i < n) d[i] = s[i];
}

extern "C" void kernel_launch(void* const* d_in, const int* in_sizes, int n_in,
                              void* d_out, int out_size) {
    const float* x = (const float*)d_in[0];
    const float* conv_w = (const float*)d_in[1];
    const float* conv_b = (const float*)d_in[2];
    const float* r1w1 = (const float*)d_in[3];
    const float* r1w2 = (const float*)d_in[4];
    const float* r2w1 = (const float*)d_in[5];
    const float* r2w2 = (const float*)d_in[6];
    const float* caw1 = (const float*)d_in[7];
    const float* caw2 = (const float*)d_in[8];
    const float* saw = (const float*)d_in[9];
    const float* Dict = (const float*)d_in[10];
    const float* Lp = (const float*)d_in[11];
    const int* nip = (const int*)d_in[12];
    float* out = (float*)d_out;

    float *l, *tb, *S, *avg, *mx, *sca, *s2m, *s2x, *satt, *lam;
    cudaGetSymbolAddress((void**)&l, g_l);
    cudaGetSymbolAddress((void**)&tb, g_t);
    cudaGetSymbolAddress((void**)&S, g_S);
    cudaGetSymbolAddress((void**)&avg, g_avg);
    cudaGetSymbolAddress((void**)&mx, g_mx);
    cudaGetSymbolAddress((void**)&sca, g_sca);
    cudaGetSymbolAddress((void**)&s2m, g_s2m);
    cudaGetSymbolAddress((void**)&s2x, g_s2x);
    cudaGetSymbolAddress((void**)&satt, g_satt);
    cudaGetSymbolAddress((void**)&lam, g_lam);

    compute_S_k<<<256, 256>>>(Dict, Lp, S);
    conv3x3_k<64, 256, false, true><<<dim3(64, 16), 256>>>(x, conv_w, conv_b, l);
    conv3x3_k<256, 128, true, false><<<dim3(64, 8), 256>>>(l, r1w1, nullptr, tb);
    conv1x1_add_k<<<dim3(64, 16), 256>>>(tb, r1w2, l);
    conv3x3_k<256, 128, true, false><<<dim3(64, 8), 256>>>(l, r2w1, nullptr, tb);
    conv1x1_add_k<<<dim3(64, 16), 256>>>(tb, r2w2, l);
    pool_k<<<2048, 256>>>(l, avg, mx);
    camlp_k<<<1, 256>>>(avg, mx, caw1, caw2, sca);
    chan_k<<<64, 256>>>(l, sca, s2m, s2x);
    sconv_k<<<128, 256>>>(s2m, s2x, saw, satt);
    lamT_k<<<dim3(1024, 8), dim3(32, 8)>>>(l, satt, Lp, lam);

    cudaFuncSetAttribute(lista_k, cudaFuncAttributeMaxDynamicSharedMemorySize,
                         LISTA_SMEM);
    lista_k<<<512, 512, LISTA_SMEM>>>(x, Dict, Lp, nip, lam, S,
                                      out, out + 8 * 256 * 4096);
    copy_k<<<64, 256>>>(Dict, out + 8 * 256 * 4096 + 8 * 64 * 4096, 64 * 256);
}

// round 6
// speedup vs baseline: 1.6107x; 1.5095x over previous
#include <cuda_runtime.h>
#include <cstdint>

__device__ float g_l[8 * 256 * 4096];
__device__ float g_t[8 * 128 * 4096];
__device__ float g_lam[8 * 4096 * 256];
__device__ float g_avg[8 * 256];
__device__ float g_mx[8 * 256];
__device__ float g_sca[8 * 256];
__device__ float g_s2m[8 * 4096];
__device__ float g_s2x[8 * 4096];
__device__ float g_satt[8 * 4096];

__device__ __forceinline__ unsigned long long pk2(float a, float b) {
    unsigned long long r;
    asm("mov.b64 %0, {%1, %2};" : "=l"(r) : "f"(a), "f"(b));
    return r;
}
__device__ __forceinline__ void upk2(unsigned long long v, float& a, float& b) {
    asm("mov.b64 {%0, %1}, %2;" : "=f"(a), "=f"(b) : "l"(v));
}
__device__ __forceinline__ void ffma2(unsigned long long& d, unsigned long long a,
                                      unsigned long long b) {
    asm("fma.rn.f32x2 %0, %1, %2, %0;" : "+l"(d) : "l"(a), "l"(b));
}
__device__ __forceinline__ unsigned long long add2(unsigned long long a,
                                                   unsigned long long b) {
    unsigned long long r;
    asm("add.rn.f32x2 %0, %1, %2;" : "=l"(r) : "l"(a), "l"(b));
    return r;
}

// direct 3x3 conv, pad=1; 256 threads x 2 pixels, 16 out-ch per block (grid.y)
template <int CI, int CO, bool RELU, bool BIAS>
__global__ __launch_bounds__(256) void conv3x3_k(const float* __restrict__ in,
                                                 const float* __restrict__ wt,
                                                 const float* __restrict__ bias,
                                                 float* __restrict__ out) {
    __shared__ __align__(16) float wsh[16 * 64 * 9];
    int tid = threadIdx.x;
    int p0 = blockIdx.x * 512 + 2 * tid;
    int b = p0 >> 12, hw = p0 & 4095, h = hw >> 6, wc = hw & 63;
    int coBase = blockIdx.y * 16;

    bool rowok[3], colok[4];
#pragma unroll
    for (int kh = 0; kh < 3; ++kh) rowok[kh] = ((unsigned)(h + kh - 1) < 64u);
#pragma unroll
    for (int q = 0; q < 4; ++q) colok[q] = ((unsigned)(wc + q - 1) < 64u);

    unsigned long long acc2[16];
#pragma unroll
    for (int q = 0; q < 8; ++q) {
        unsigned long long bi =
            BIAS ? pk2(bias[coBase + 2 * q], bias[coBase + 2 * q + 1]) : 0ULL;
        acc2[2 * q] = bi;
        acc2[2 * q + 1] = bi;
    }

    const float* inb = in + (size_t)b * CI * 4096;
    for (int cc = 0; cc < CI / 64; ++cc) {
        __syncthreads();
        for (int i = tid; i < 16 * 64 * 9; i += 256) {
            int o = i / 576, r = i - o * 576;
            wsh[r * 16 + o] = wt[(size_t)(coBase + o) * (CI * 9) + cc * 576 + r];
        }
        __syncthreads();
        const float* inc = inb + (size_t)cc * 64 * 4096;
#pragma unroll 1
        for (int ci = 0; ci < 64; ++ci) {
            const float* ip = inc + (size_t)ci * 4096;
            float rv[3][4];
#pragma unroll
            for (int kh = 0; kh < 3; ++kh) {
                int rbase = (h + kh - 1) * 64 + wc - 1;
#pragma unroll
                for (int q = 0; q < 4; ++q) {
                    float u = (rowok[kh] && colok[q]) ? ip[rbase + q] : 0.f;
                    rv[kh][q] = RELU ? fmaxf(u, 0.f) : u;
                }
            }
#pragma unroll
            for (int kh = 0; kh < 3; ++kh)
#pragma unroll
                for (int kw = 0; kw < 3; ++kw) {
                    unsigned long long v0 = pk2(rv[kh][kw], rv[kh][kw]);
                    unsigned long long v1 = pk2(rv[kh][kw + 1], rv[kh][kw + 1]);
                    const ulonglong2* wp =
                        (const ulonglong2*)&wsh[(ci * 9 + kh * 3 + kw) * 16];
#pragma unroll
                    for (int q = 0; q < 4; ++q) {
                        ulonglong2 wq = wp[q];
                        ffma2(acc2[4 * q], wq.x, v0);
                        ffma2(acc2[4 * q + 1], wq.x, v1);
                        ffma2(acc2[4 * q + 2], wq.y, v0);
                        ffma2(acc2[4 * q + 3], wq.y, v1);
                    }
                }
        }
    }
    size_t ob = ((size_t)b * CO + coBase) * 4096 + hw;
#pragma unroll
    for (int q = 0; q < 8; ++q) {
        float a0, a1, b0_, b1_;
        upk2(acc2[2 * q], a0, b0_);
        upk2(acc2[2 * q + 1], a1, b1_);
        out[ob + (size_t)(2 * q) * 4096] = a0;
        out[ob + (size_t)(2 * q) * 4096 + 1] = a1;
        out[ob + (size_t)(2 * q + 1) * 4096] = b0_;
        out[ob + (size_t)(2 * q + 1) * 4096 + 1] = b1_;
    }
}

// 1x1 conv (relu(t)@w2) + residual add; CI=128, 16 co per block, 2 px/thread
__global__ __launch_bounds__(256) void conv1x1_add_k(const float* __restrict__ tin,
                                                     const float* __restrict__ wt,
                                                     float* __restrict__ lio) {
    __shared__ __align__(16) float wsh[128 * 16];
    int tid = threadIdx.x;
    int p0 = blockIdx.x * 512 + 2 * tid;
    int b = p0 >> 12, hw = p0 & 4095;
    int coBase = blockIdx.y * 16;
    for (int i = tid; i < 2048; i += 256) {
        int o = i >> 7, ci = i & 127;
        wsh[ci * 16 + o] = wt[(size_t)(coBase + o) * 128 + ci];
    }
    __syncthreads();
    unsigned long long acc2[16];
    size_t lb = ((size_t)b * 256 + coBase) * 4096 + hw;
#pragma unroll
    for (int q = 0; q < 8; ++q) {
        float2 v = *(const float2*)&lio[lb + (size_t)(2 * q) * 4096];
        float2 u = *(const float2*)&lio[lb + (size_t)(2 * q + 1) * 4096];
        acc2[2 * q] = pk2(v.x, u.x);
        acc2[2 * q + 1] = pk2(v.y, u.y);
    }
    const float* tb = tin + (size_t)b * 128 * 4096 + hw;
#pragma unroll 1
    for (int ci = 0; ci < 128; ci += 8) {
        float2 v[8];
#pragma unroll
        for (int j = 0; j < 8; ++j) {
            float2 u = *(const float2*)&tb[(size_t)(ci + j) * 4096];
            v[j].x = fmaxf(u.x, 0.f);
            v[j].y = fmaxf(u.y, 0.f);
        }
#pragma unroll
        for (int j = 0; j < 8; ++j) {
            unsigned long long v0 = pk2(v[j].x, v[j].x);
            unsigned long long v1 = pk2(v[j].y, v[j].y);
            const ulonglong2* wp = (const ulonglong2*)&wsh[(ci + j) * 16];
#pragma unroll
            for (int q = 0; q < 4; ++q) {
                ulonglong2 wq = wp[q];
                ffma2(acc2[4 * q], wq.x, v0);
                ffma2(acc2[4 * q + 1], wq.x, v1);
                ffma2(acc2[4 * q + 2], wq.y, v0);
                ffma2(acc2[4 * q + 3], wq.y, v1);
            }
        }
    }
#pragma unroll
    for (int q = 0; q < 8; ++q) {
        float a0, a1, b0_, b1_;
        upk2(acc2[2 * q], a0, b0_);
        upk2(acc2[2 * q + 1], a1, b1_);
        float2 o0 = {a0, a1}, o1 = {b0_, b1_};
        *(float2*)&lio[lb + (size_t)(2 * q) * 4096] = o0;
        *(float2*)&lio[lb + (size_t)(2 * q + 1) * 4096] = o1;
    }
}

__global__ __launch_bounds__(256) void pool_k(const float* __restrict__ l,
                                              float* __restrict__ avg,
                                              float* __restrict__ mx) {
    __shared__ float ss[256], sm[256];
    int bc = blockIdx.x, t = threadIdx.x;
    const float4* p = (const float4*)(l + (size_t)bc * 4096);
    float s = 0.f, m = -3.4e38f;
    for (int i = t; i < 1024; i += 256) {
        float4 v = p[i];
        s += v.x + v.y + v.z + v.w;
        m = fmaxf(m, fmaxf(fmaxf(v.x, v.y), fmaxf(v.z, v.w)));
    }
    ss[t] = s;
    sm[t] = m;
    __syncthreads();
    for (int st = 128; st > 0; st >>= 1) {
        if (t < st) {
            ss[t] += ss[t + st];
            sm[t] = fmaxf(sm[t], sm[t + st]);
        }
        __syncthreads();
    }
    if (t == 0) {
        avg[bc] = ss[0] * (1.f / 4096.f);
        mx[bc] = sm[0];
    }
}

__global__ void camlp_k(const float* __restrict__ avg, const float* __restrict__ mx,
                        const float* __restrict__ w1, const float* __restrict__ w2,
                        float* __restrict__ sca) {
    __shared__ float hsh[128];
    int t = threadIdx.x;
    if (t < 128) {
        int b = t >> 4, j = t & 15;
        float a = 0.f, m = 0.f;
        for (int c = 0; c < 256; ++c) {
            float w = w1[j * 256 + c];
            a += avg[b * 256 + c] * w;
            m += mx[b * 256 + c] * w;
        }
        hsh[b * 16 + j] = fmaxf(a, 0.f) + fmaxf(m, 0.f);
    }
    __syncthreads();
    for (int b = 0; b < 8; ++b) {
        float o = 0.f;
#pragma unroll
        for (int j = 0; j < 16; ++j) o += hsh[b * 16 + j] * w2[t * 16 + j];
        sca[b * 256 + t] = 1.f / (1.f + expf(-o));
    }
}

__global__ __launch_bounds__(256) void chan_k(float* __restrict__ l,
                                              const float* __restrict__ sca,
                                              float* __restrict__ s2m,
                                              float* __restrict__ s2x) {
    int tid = threadIdx.x;
    int p0 = blockIdx.x * 512 + 2 * tid;
    int b = p0 >> 12, hw = p0 & 4095;
    size_t base = (size_t)b * 256 * 4096 + hw;
    float s0 = 0.f, s1 = 0.f, m0 = -3.4e38f, m1 = -3.4e38f;
#pragma unroll 1
    for (int c = 0; c < 256; c += 8) {
        float2 v[8];
#pragma unroll
        for (int j = 0; j < 8; ++j) {
            float2 u = *(float2*)&l[base + (size_t)(c + j) * 4096];
            float sc = sca[b * 256 + c + j];
            v[j].x = u.x * sc;
            v[j].y = u.y * sc;
        }
#pragma unroll
        for (int j = 0; j < 8; ++j) {
            *(float2*)&l[base + (size_t)(c + j) * 4096] = v[j];
            s0 += v[j].x;
            s1 += v[j].y;
            m0 = fmaxf(m0, v[j].x);
            m1 = fmaxf(m1, v[j].y);
        }
    }
    s2m[p0] = s0 * (1.f / 256.f);
    s2m[p0 + 1] = s1 * (1.f / 256.f);
    s2x[p0] = m0;
    s2x[p0 + 1] = m1;
}

__global__ void sconv_k(const float* __restrict__ s2m, const float* __restrict__ s2x,
                        const float* __restrict__ sw, float* __restrict__ satt) {
    int p = blockIdx.x * 256 + threadIdx.x;
    int b = p >> 12, hw = p & 4095, h = hw >> 6, w = hw & 63;
    float a = 0.f;
#pragma unroll
    for (int kh = 0; kh < 3; ++kh) {
        int hh = h + kh - 1;
        if ((unsigned)hh >= 64u) continue;
#pragma unroll
        for (int kw = 0; kw < 3; ++kw) {
            int ww = w + kw - 1;
            if ((unsigned)ww >= 64u) continue;
            int q = b * 4096 + hh * 64 + ww;
            a += s2m[q] * sw[kh * 3 + kw] + s2x[q] * sw[9 + kh * 3 + kw];
        }
    }
    satt[p] = 1.f / (1.f + expf(-a));
}

// lam NHWC = (l * satt) / L, tiled transpose
__global__ void lamT_k(const float* __restrict__ l, const float* __restrict__ satt,
                       const float* __restrict__ Lp, float* __restrict__ lam) {
    __shared__ float tile[32][33];
    int pb = blockIdx.x * 32, cb = blockIdx.y * 32;
    int tx = threadIdx.x, ty = threadIdx.y;
    int b = pb >> 12, pl = pb & 4095;
#pragma unroll
    for (int k = 0; k < 4; ++k) {
        int c = cb + ty + 8 * k;
        tile[ty + 8 * k][tx] = l[((size_t)b * 256 + c) * 4096 + pl + tx];
    }
    __syncthreads();
    float invL = 1.f / Lp[0];
#pragma unroll
    for (int k = 0; k < 4; ++k) {
        int p2 = pb + ty + 8 * k;
        float sc = satt[p2] * invL;
        lam[(size_t)p2 * 256 + cb + tx] = tile[tx][ty + 8 * k] * sc;
    }
}

// ---------------------------------------------------------------------------
// Factorized LISTA: z' = soft(yL + z - (z @ Dict^T) @ Dict / L, lam)
// 64 pixels/CTA, 512 threads; Dict fully SMEM-resident; no S matrix.
// ---------------------------------------------------------------------------
#define ZS 66
#define RS 68
#define D1S 68
#define ZTR_OFF 0
#define RT_OFF 16896
#define D1_OFF (16896 + 4352)
#define D2_OFF (16896 + 4352 + 17408)
#define LISTA_SMEM ((16896 + 4352 + 17408 + 16384) * 4)

__global__ __launch_bounds__(512, 1) void lista_k(
    const float* __restrict__ x, const float* __restrict__ Dict,
    const float* __restrict__ Lp, const int* __restrict__ nip,
    const float* __restrict__ lam_g,
    float* __restrict__ out_z, float* __restrict__ out_r) {
    extern __shared__ __align__(16) float smem[];
    float* ztr = smem + ZTR_OFF;  // [256 a][ZS] z (k-major)
    float* rt = smem + RT_OFF;    // [64 c][RS] r transposed (also x staging)
    float* d1 = smem + D1_OFF;    // [256 a][D1S] Dict[c][a] transposed
    float* d2 = smem + D2_OFF;    // [64 c][256 a] Dict
    int t = threadIdx.x;
    int atom = t & 255, half = t >> 8, mb = half * 32;
    int m1 = t & 63, cg = t >> 6;  // step1 mapping
    int pbase = blockIdx.x * 64;
    int b = pbase >> 12, pl = pbase & 4095;
    float invL = 1.f / Lp[0];
    int niters = nip[0];

    // stage x into rt as [c][m]; Dict into d1 ([a][c]) and d2 ([c][a])
    size_t xofs = (size_t)b * 64 * 4096 + pl;
    for (int i = t; i < 4096; i += 512) {
        int c = i >> 6, m = i & 63;
        rt[c * RS + m] = x[xofs + (size_t)c * 4096 + m];
    }
    for (int i = t; i < 16384; i += 512) {
        int c = i >> 8, a = i & 255;
        float d = Dict[i];
        d1[a * D1S + c] = d;
        d2[i] = d;
    }
    __syncthreads();

    // per-thread lambda (32 regs)
    float lamreg[32];
    {
        const float* lg = lam_g + ((size_t)(pbase + mb)) * 256 + atom;
#pragma unroll
        for (int m = 0; m < 32; ++m) lamreg[m] = lg[(size_t)m * 256];
    }

    // y = x @ Dict ; yL in regs, z0 -> ztr
    unsigned long long ylpk[16];
    {
        unsigned long long acc2[16];
#pragma unroll
        for (int j = 0; j < 16; ++j) acc2[j] = 0ULL;
#pragma unroll 1
        for (int c = 0; c < 64; ++c) {
            float dg = Dict[c * 256 + atom];
            unsigned long long dd = pk2(dg, dg);
            const ulonglong2* xp = (const ulonglong2*)(rt + c * RS + mb);
#pragma unroll
            for (int i = 0; i < 8; ++i) {
                ulonglong2 q = xp[i];
                ffma2(acc2[2 * i], q.x, dd);
                ffma2(acc2[2 * i + 1], q.y, dd);
            }
        }
        unsigned long long il2 = pk2(invL, invL);
#pragma unroll
        for (int j = 0; j < 16; ++j) {
            float y0, y1;
            upk2(acc2[j], y0, y1);
            ylpk[j] = pk2(y0 * invL, y1 * invL);
            float g0 = fmaxf(fabsf(y0) - lamreg[2 * j], 0.f);
            float g1 = fmaxf(fabsf(y1) - lamreg[2 * j + 1], 0.f);
            float z0 = (y0 > 0.f) ? g0 : -g0;
            float z1 = (y1 > 0.f) ? g1 : -g1;
            *(unsigned long long*)&ztr[atom * ZS + mb + 2 * j] = pk2(z0, z1);
        }
        (void)il2;
    }
    __syncthreads();

    unsigned long long nil2 = pk2(-invL, -invL);

    for (int it = 0; it <= niters; ++it) {
        // step1: r[c][m] = sum_a z[a][m] * d1[a][c]  (thread: 8 c, 1 m)
        {
            unsigned long long acc2[4];
#pragma unroll
            for (int q = 0; q < 4; ++q) acc2[q] = 0ULL;
            const float* zp = ztr + m1;
            const ulonglong2* dp = (const ulonglong2*)(d1 + cg * 8);
#pragma unroll 2
            for (int a = 0; a < 256; ++a) {
                float zv = zp[a * ZS];
                unsigned long long vv = pk2(zv, zv);
                ulonglong2 q0 = dp[a * (D1S / 4)];
                ulonglong2 q1 = dp[a * (D1S / 4) + 1];
                ffma2(acc2[0], q0.x, vv);
                ffma2(acc2[1], q0.y, vv);
                ffma2(acc2[2], q1.x, vv);
                ffma2(acc2[3], q1.y, vv);
            }
#pragma unroll
            for (int q = 0; q < 4; ++q) {
                float r0, r1;
                upk2(acc2[q], r0, r1);
                rt[(cg * 8 + 2 * q) * RS + m1] = r0;
                rt[(cg * 8 + 2 * q + 1) * RS + m1] = r1;
            }
        }
        __syncthreads();
        if (it == niters) break;  // final step1 produced x_recon in rt

        // step2: z'[a][m] = soft(yL + z - invL * sum_c r[c][m] d2[c][a])
        {
            unsigned long long acc2[16];
#pragma unroll
            for (int j = 0; j < 16; ++j) acc2[j] = 0ULL;
#pragma unroll 1
            for (int c = 0; c < 64; ++c) {
                float dg = d2[c * 256 + atom];
                unsigned long long dd = pk2(dg, dg);
                const ulonglong2* rp = (const ulonglong2*)(rt + c * RS + mb);
#pragma unroll
                for (int i = 0; i < 8; ++i) {
                    ulonglong2 q = rp[i];
                    ffma2(acc2[2 * i], q.x, dd);
                    ffma2(acc2[2 * i + 1], q.y, dd);
                }
            }
#pragma unroll
            for (int j = 0; j < 16; ++j) {
                unsigned long long zold =
                    *(unsigned long long*)&ztr[atom * ZS + mb + 2 * j];
                unsigned long long w = add2(ylpk[j], zold);
                ffma2(w, acc2[j], nil2);  // w = yl + z - invL*proj
                float v0, v1;
                upk2(w, v0, v1);
                float g0 = fmaxf(fabsf(v0) - lamreg[2 * j], 0.f);
                float g1 = fmaxf(fabsf(v1) - lamreg[2 * j + 1], 0.f);
                float z0 = (v0 > 0.f) ? g0 : -g0;
                float z1 = (v1 > 0.f) ? g1 : -g1;
                *(unsigned long long*)&ztr[atom * ZS + mb + 2 * j] = pk2(z0, z1);
            }
        }
        __syncthreads();
    }

    // outputs: z from ztr, x_recon from rt
    size_t zofs = (size_t)b * 256 * 4096 + pl;
    for (int i = t; i < 16384; i += 512) {
        int a = i >> 6, m = i & 63;
        out_z[zofs + (size_t)a * 4096 + m] = ztr[a * ZS + m];
    }
    size_t rofs = (size_t)b * 64 * 4096 + pl;
    for (int i = t; i < 4096; i += 512) {
        int c = i >> 6, m = i & 63;
        out_r[rofs + (size_t)c * 4096 + m] = rt[c * RS + m];
    }
}

__global__ void copy_k(const float* __restrict__ s, float* __restrict__ d, int n) {
    int i = blockIdx.x * blockDim.x + threadIdx.x;
    if (i < n) d[i] = s[i];
}

extern "C" void kernel_launch(void* const* d_in, const int* in_sizes, int n_in,
                              void* d_out, int out_size) {
    const float* x = (const float*)d_in[0];
    const float* conv_w = (const float*)d_in[1];
    const float* conv_b = (const float*)d_in[2];
    const float* r1w1 = (const float*)d_in[3];
    const float* r1w2 = (const float*)d_in[4];
    const float* r2w1 = (const float*)d_in[5];
    const float* r2w2 = (const float*)d_in[6];
    const float* caw1 = (const float*)d_in[7];
    const float* caw2 = (const float*)d_in[8];
    const float* saw = (const float*)d_in[9];
    const float* Dict = (const float*)d_in[10];
    const float* Lp = (const float*)d_in[11];
    const int* nip = (const int*)d_in[12];
    float* out = (float*)d_out;

    float *l, *tb, *avg, *mx, *sca, *s2m, *s2x, *satt, *lam;
    cudaGetSymbolAddress((void**)&l, g_l);
    cudaGetSymbolAddress((void**)&tb, g_t);
    cudaGetSymbolAddress((void**)&avg, g_avg);
    cudaGetSymbolAddress((void**)&mx, g_mx);
    cudaGetSymbolAddress((void**)&sca, g_sca);
    cudaGetSymbolAddress((void**)&s2m, g_s2m);
    cudaGetSymbolAddress((void**)&s2x, g_s2x);
    cudaGetSymbolAddress((void**)&satt, g_satt);
    cudaGetSymbolAddress((void**)&lam, g_lam);

    conv3x3_k<64, 256, false, true><<<dim3(64, 16), 256>>>(x, conv_w, conv_b, l);
    conv3x3_k<256, 128, true, false><<<dim3(64, 8), 256>>>(l, r1w1, nullptr, tb);
    conv1x1_add_k<<<dim3(64, 16), 256>>>(tb, r1w2, l);
    conv3x3_k<256, 128, true, false><<<dim3(64, 8), 256>>>(l, r2w1, nullptr, tb);
    conv1x1_add_k<<<dim3(64, 16), 256>>>(tb, r2w2, l);
    pool_k<<<2048, 256>>>(l, avg, mx);
    camlp_k<<<1, 256>>>(avg, mx, caw1, caw2, sca);
    chan_k<<<64, 256>>>(l, sca, s2m, s2x);
    sconv_k<<<128, 256>>>(s2m, s2x, saw, satt);
    lamT_k<<<dim3(1024, 8), dim3(32, 8)>>>(l, satt, Lp, lam);

    cudaFuncSetAttribute(lista_k, cudaFuncAttributeMaxDynamicSharedMemorySize,
                         LISTA_SMEM);
    lista_k<<<512, 512, LISTA_SMEM>>>(x, Dict, Lp, nip, lam,
                                      out, out + 8 * 256 * 4096);
    copy_k<<<64, 256>>>(Dict, out + 8 * 256 * 4096 + 8 * 64 * 4096, 64 * 256);
}

// round 7
// speedup vs baseline: 1.7118x; 1.0628x over previous
#include <cuda_runtime.h>
#include <cstdint>

__device__ float g_l[8 * 256 * 4096];
__device__ float g_t[8 * 128 * 4096];
__device__ float g_lam[8 * 4096 * 256];
__device__ float g_avg[8 * 256];
__device__ float g_mx[8 * 256];
__device__ float g_sca[8 * 256];
__device__ float g_s2m[8 * 4096];
__device__ float g_s2x[8 * 4096];
__device__ float g_satt[8 * 4096];

__device__ __forceinline__ unsigned long long pk2(float a, float b) {
    unsigned long long r;
    asm("mov.b64 %0, {%1, %2};" : "=l"(r) : "f"(a), "f"(b));
    return r;
}
__device__ __forceinline__ void upk2(unsigned long long v, float& a, float& b) {
    asm("mov.b64 {%0, %1}, %2;" : "=f"(a), "=f"(b) : "l"(v));
}
__device__ __forceinline__ void ffma2(unsigned long long& d, unsigned long long a,
                                      unsigned long long b) {
    asm("fma.rn.f32x2 %0, %1, %2, %0;" : "+l"(d) : "l"(a), "l"(b));
}
__device__ __forceinline__ unsigned long long add2(unsigned long long a,
                                                   unsigned long long b) {
    unsigned long long r;
    asm("add.rn.f32x2 %0, %1, %2;" : "=l"(r) : "l"(a), "l"(b));
    return r;
}

// direct 3x3 conv, pad=1; 256 threads x (2x2 pixels), 16 out-ch per block.
// block covers 16 rows x 64 cols; grid.x = 8 batch * 4 row-blocks.
template <int CI, int CO, bool RELU, bool BIAS>
__global__ __launch_bounds__(256) void conv3x3_k(const float* __restrict__ in,
                                                 const float* __restrict__ wt,
                                                 const float* __restrict__ bias,
                                                 float* __restrict__ out) {
    __shared__ __align__(16) float wsh[16 * 64 * 9];
    int tid = threadIdx.x;
    int b = blockIdx.x >> 2, rb = blockIdx.x & 3;
    int w0 = (tid & 31) * 2, h0 = rb * 16 + (tid >> 5) * 2;
    int coBase = blockIdx.y * 16;

    bool rok[4], cok[4];
#pragma unroll
    for (int r = 0; r < 4; ++r) rok[r] = ((unsigned)(h0 - 1 + r) < 64u);
#pragma unroll
    for (int q = 0; q < 4; ++q) cok[q] = ((unsigned)(w0 - 1 + q) < 64u);

    // acc2[p*4 + px]: co pair (2p,2p+1), pixel px = dh*2+dw
    unsigned long long acc2[32];
#pragma unroll
    for (int p = 0; p < 8; ++p) {
        unsigned long long bi =
            BIAS ? pk2(bias[coBase + 2 * p], bias[coBase + 2 * p + 1]) : 0ULL;
#pragma unroll
        for (int px = 0; px < 4; ++px) acc2[p * 4 + px] = bi;
    }

    const float* inb = in + (size_t)b * CI * 4096;
    for (int cc = 0; cc < CI / 64; ++cc) {
        __syncthreads();
        for (int i = tid; i < 16 * 64 * 9; i += 256) {
            int o = i / 576, r = i - o * 576;
            wsh[r * 16 + o] = wt[(size_t)(coBase + o) * (CI * 9) + cc * 576 + r];
        }
        __syncthreads();
        const float* inc = inb + (size_t)cc * 64 * 4096;
#pragma unroll 1
        for (int ci = 0; ci < 64; ++ci) {
            const float* ip = inc + (size_t)ci * 4096;
            float rv[4][4];
#pragma unroll
            for (int r = 0; r < 4; ++r) {
                int rbase = (h0 - 1 + r) * 64 + w0 - 1;
#pragma unroll
                for (int q = 0; q < 4; ++q) {
                    float u = (rok[r] && cok[q]) ? ip[rbase + q] : 0.f;
                    rv[r][q] = RELU ? fmaxf(u, 0.f) : u;
                }
            }
#pragma unroll
            for (int kh = 0; kh < 3; ++kh)
#pragma unroll
                for (int kw = 0; kw < 3; ++kw) {
                    const ulonglong2* wp =
                        (const ulonglong2*)&wsh[(ci * 9 + kh * 3 + kw) * 16];
                    ulonglong2 wq0 = wp[0], wq1 = wp[1], wq2 = wp[2], wq3 = wp[3];
#pragma unroll
                    for (int dh = 0; dh < 2; ++dh)
#pragma unroll
                        for (int dw = 0; dw < 2; ++dw) {
                            float v = rv[kh + dh][kw + dw];
                            unsigned long long vv = pk2(v, v);
                            int px = dh * 2 + dw;
                            ffma2(acc2[0 * 4 + px], wq0.x, vv);
                            ffma2(acc2[1 * 4 + px], wq0.y, vv);
                            ffma2(acc2[2 * 4 + px], wq1.x, vv);
                            ffma2(acc2[3 * 4 + px], wq1.y, vv);
                            ffma2(acc2[4 * 4 + px], wq2.x, vv);
                            ffma2(acc2[5 * 4 + px], wq2.y, vv);
                            ffma2(acc2[6 * 4 + px], wq3.x, vv);
                            ffma2(acc2[7 * 4 + px], wq3.y, vv);
                        }
                }
        }
    }
    size_t ob = ((size_t)b * CO + coBase) * 4096 + (size_t)h0 * 64 + w0;
#pragma unroll
    for (int p = 0; p < 8; ++p) {
        float a00, b00, a01, b01, a10, b10, a11, b11;
        upk2(acc2[p * 4 + 0], a00, b00);
        upk2(acc2[p * 4 + 1], a01, b01);
        upk2(acc2[p * 4 + 2], a10, b10);
        upk2(acc2[p * 4 + 3], a11, b11);
        float2 r0 = {a00, a01}, r1 = {a10, a11};
        float2 s0 = {b00, b01}, s1 = {b10, b11};
        *(float2*)&out[ob + (size_t)(2 * p) * 4096] = r0;
        *(float2*)&out[ob + (size_t)(2 * p) * 4096 + 64] = r1;
        *(float2*)&out[ob + (size_t)(2 * p + 1) * 4096] = s0;
        *(float2*)&out[ob + (size_t)(2 * p + 1) * 4096 + 64] = s1;
    }
}

// 1x1 conv (relu(t)@w2) + residual add; CI=128, 16 co per block, 2 px/thread
__global__ __launch_bounds__(256) void conv1x1_add_k(const float* __restrict__ tin,
                                                     const float* __restrict__ wt,
                                                     float* __restrict__ lio) {
    __shared__ __align__(16) float wsh[128 * 16];
    int tid = threadIdx.x;
    int p0 = blockIdx.x * 512 + 2 * tid;
    int b = p0 >> 12, hw = p0 & 4095;
    int coBase = blockIdx.y * 16;
    for (int i = tid; i < 2048; i += 256) {
        int o = i >> 7, ci = i & 127;
        wsh[ci * 16 + o] = wt[(size_t)(coBase + o) * 128 + ci];
    }
    __syncthreads();
    unsigned long long acc2[16];
    size_t lb = ((size_t)b * 256 + coBase) * 4096 + hw;
#pragma unroll
    for (int q = 0; q < 8; ++q) {
        float2 v = *(const float2*)&lio[lb + (size_t)(2 * q) * 4096];
        float2 u = *(const float2*)&lio[lb + (size_t)(2 * q + 1) * 4096];
        acc2[2 * q] = pk2(v.x, u.x);
        acc2[2 * q + 1] = pk2(v.y, u.y);
    }
    const float* tb = tin + (size_t)b * 128 * 4096 + hw;
#pragma unroll 1
    for (int ci = 0; ci < 128; ci += 8) {
        float2 v[8];
#pragma unroll
        for (int j = 0; j < 8; ++j) {
            float2 u = *(const float2*)&tb[(size_t)(ci + j) * 4096];
            v[j].x = fmaxf(u.x, 0.f);
            v[j].y = fmaxf(u.y, 0.f);
        }
#pragma unroll
        for (int j = 0; j < 8; ++j) {
            unsigned long long v0 = pk2(v[j].x, v[j].x);
            unsigned long long v1 = pk2(v[j].y, v[j].y);
            const ulonglong2* wp = (const ulonglong2*)&wsh[(ci + j) * 16];
#pragma unroll
            for (int q = 0; q < 4; ++q) {
                ulonglong2 wq = wp[q];
                ffma2(acc2[4 * q], wq.x, v0);
                ffma2(acc2[4 * q + 1], wq.x, v1);
                ffma2(acc2[4 * q + 2], wq.y, v0);
                ffma2(acc2[4 * q + 3], wq.y, v1);
            }
        }
    }
#pragma unroll
    for (int q = 0; q < 8; ++q) {
        float a0, a1, b0_, b1_;
        upk2(acc2[2 * q], a0, b0_);
        upk2(acc2[2 * q + 1], a1, b1_);
        float2 o0 = {a0, a1}, o1 = {b0_, b1_};
        *(float2*)&lio[lb + (size_t)(2 * q) * 4096] = o0;
        *(float2*)&lio[lb + (size_t)(2 * q + 1) * 4096] = o1;
    }
}

__global__ __launch_bounds__(256) void pool_k(const float* __restrict__ l,
                                              float* __restrict__ avg,
                                              float* __restrict__ mx) {
    __shared__ float ss[256], sm[256];
    int bc = blockIdx.x, t = threadIdx.x;
    const float4* p = (const float4*)(l + (size_t)bc * 4096);
    float s = 0.f, m = -3.4e38f;
    for (int i = t; i < 1024; i += 256) {
        float4 v = p[i];
        s += v.x + v.y + v.z + v.w;
        m = fmaxf(m, fmaxf(fmaxf(v.x, v.y), fmaxf(v.z, v.w)));
    }
    ss[t] = s;
    sm[t] = m;
    __syncthreads();
    for (int st = 128; st > 0; st >>= 1) {
        if (t < st) {
            ss[t] += ss[t + st];
            sm[t] = fmaxf(sm[t], sm[t + st]);
        }
        __syncthreads();
    }
    if (t == 0) {
        avg[bc] = ss[0] * (1.f / 4096.f);
        mx[bc] = sm[0];
    }
}

__global__ void camlp_k(const float* __restrict__ avg, const float* __restrict__ mx,
                        const float* __restrict__ w1, const float* __restrict__ w2,
                        float* __restrict__ sca) {
    __shared__ float hsh[128];
    int t = threadIdx.x;
    if (t < 128) {
        int b = t >> 4, j = t & 15;
        float a = 0.f, m = 0.f;
        for (int c = 0; c < 256; ++c) {
            float w = w1[j * 256 + c];
            a += avg[b * 256 + c] * w;
            m += mx[b * 256 + c] * w;
        }
        hsh[b * 16 + j] = fmaxf(a, 0.f) + fmaxf(m, 0.f);
    }
    __syncthreads();
    for (int b = 0; b < 8; ++b) {
        float o = 0.f;
#pragma unroll
        for (int j = 0; j < 16; ++j) o += hsh[b * 16 + j] * w2[t * 16 + j];
        sca[b * 256 + t] = 1.f / (1.f + expf(-o));
    }
}

__global__ __launch_bounds__(256) void chan_k(float* __restrict__ l,
                                              const float* __restrict__ sca,
                                              float* __restrict__ s2m,
                                              float* __restrict__ s2x) {
    int tid = threadIdx.x;
    int p0 = blockIdx.x * 512 + 2 * tid;
    int b = p0 >> 12, hw = p0 & 4095;
    size_t base = (size_t)b * 256 * 4096 + hw;
    float s0 = 0.f, s1 = 0.f, m0 = -3.4e38f, m1 = -3.4e38f;
#pragma unroll 1
    for (int c = 0; c < 256; c += 8) {
        float2 v[8];
#pragma unroll
        for (int j = 0; j < 8; ++j) {
            float2 u = *(float2*)&l[base + (size_t)(c + j) * 4096];
            float sc = sca[b * 256 + c + j];
            v[j].x = u.x * sc;
            v[j].y = u.y * sc;
        }
#pragma unroll
        for (int j = 0; j < 8; ++j) {
            *(float2*)&l[base + (size_t)(c + j) * 4096] = v[j];
            s0 += v[j].x;
            s1 += v[j].y;
            m0 = fmaxf(m0, v[j].x);
            m1 = fmaxf(m1, v[j].y);
        }
    }
    s2m[p0] = s0 * (1.f / 256.f);
    s2m[p0 + 1] = s1 * (1.f / 256.f);
    s2x[p0] = m0;
    s2x[p0 + 1] = m1;
}

__global__ void sconv_k(const float* __restrict__ s2m, const float* __restrict__ s2x,
                        const float* __restrict__ sw, float* __restrict__ satt) {
    int p = blockIdx.x * 256 + threadIdx.x;
    int b = p >> 12, hw = p & 4095, h = hw >> 6, w = hw & 63;
    float a = 0.f;
#pragma unroll
    for (int kh = 0; kh < 3; ++kh) {
        int hh = h + kh - 1;
        if ((unsigned)hh >= 64u) continue;
#pragma unroll
        for (int kw = 0; kw < 3; ++kw) {
            int ww = w + kw - 1;
            if ((unsigned)ww >= 64u) continue;
            int q = b * 4096 + hh * 64 + ww;
            a += s2m[q] * sw[kh * 3 + kw] + s2x[q] * sw[9 + kh * 3 + kw];
        }
    }
    satt[p] = 1.f / (1.f + expf(-a));
}

// lam NHWC = (l * satt) / L, tiled transpose
__global__ void lamT_k(const float* __restrict__ l, const float* __restrict__ satt,
                       const float* __restrict__ Lp, float* __restrict__ lam) {
    __shared__ float tile[32][33];
    int pb = blockIdx.x * 32, cb = blockIdx.y * 32;
    int tx = threadIdx.x, ty = threadIdx.y;
    int b = pb >> 12, pl = pb & 4095;
#pragma unroll
    for (int k = 0; k < 4; ++k) {
        int c = cb + ty + 8 * k;
        tile[ty + 8 * k][tx] = l[((size_t)b * 256 + c) * 4096 + pl + tx];
    }
    __syncthreads();
    float invL = 1.f / Lp[0];
#pragma unroll
    for (int k = 0; k < 4; ++k) {
        int p2 = pb + ty + 8 * k;
        float sc = satt[p2] * invL;
        lam[(size_t)p2 * 256 + cb + tx] = tile[tx][ty + 8 * k] * sc;
    }
}

// ---------------------------------------------------------------------------
// Factorized LISTA: z' = soft(yL + z - (z @ Dict^T) @ Dict / L, lam)
// 64 pixels/CTA, 512 threads; Dict fully SMEM-resident; no S matrix.
// ---------------------------------------------------------------------------
#define ZS 66
#define RS 68
#define D1S 68
#define ZTR_OFF 0
#define RT_OFF 16896
#define D1_OFF (16896 + 4352)
#define D2_OFF (16896 + 4352 + 17408)
#define LISTA_SMEM ((16896 + 4352 + 17408 + 16384) * 4)

__global__ __launch_bounds__(512, 1) void lista_k(
    const float* __restrict__ x, const float* __restrict__ Dict,
    const float* __restrict__ Lp, const int* __restrict__ nip,
    const float* __restrict__ lam_g,
    float* __restrict__ out_z, float* __restrict__ out_r) {
    extern __shared__ __align__(16) float smem[];
    float* ztr = smem + ZTR_OFF;  // [256 a][ZS] z (k-major)
    float* rt = smem + RT_OFF;    // [64 c][RS] r transposed (also x staging)
    float* d1 = smem + D1_OFF;    // [256 a][D1S] Dict[c][a] transposed
    float* d2 = smem + D2_OFF;    // [64 c][256 a] Dict
    int t = threadIdx.x;
    int atom = t & 255, half = t >> 8, mb = half * 32;
    int m1 = t & 63, cg = t >> 6;  // step1 mapping
    int pbase = blockIdx.x * 64;
    int b = pbase >> 12, pl = pbase & 4095;
    float invL = 1.f / Lp[0];
    int niters = nip[0];

    size_t xofs = (size_t)b * 64 * 4096 + pl;
    for (int i = t; i < 4096; i += 512) {
        int c = i >> 6, m = i & 63;
        rt[c * RS + m] = x[xofs + (size_t)c * 4096 + m];
    }
    for (int i = t; i < 16384; i += 512) {
        int c = i >> 8, a = i & 255;
        float d = Dict[i];
        d1[a * D1S + c] = d;
        d2[i] = d;
    }
    __syncthreads();

    float lamreg[32];
    {
        const float* lg = lam_g + ((size_t)(pbase + mb)) * 256 + atom;
#pragma unroll
        for (int m = 0; m < 32; ++m) lamreg[m] = lg[(size_t)m * 256];
    }

    unsigned long long ylpk[16];
    {
        unsigned long long acc2[16];
#pragma unroll
        for (int j = 0; j < 16; ++j) acc2[j] = 0ULL;
#pragma unroll 1
        for (int c = 0; c < 64; ++c) {
            float dg = Dict[c * 256 + atom];
            unsigned long long dd = pk2(dg, dg);
            const ulonglong2* xp = (const ulonglong2*)(rt + c * RS + mb);
#pragma unroll
            for (int i = 0; i < 8; ++i) {
                ulonglong2 q = xp[i];
                ffma2(acc2[2 * i], q.x, dd);
                ffma2(acc2[2 * i + 1], q.y, dd);
            }
        }
#pragma unroll
        for (int j = 0; j < 16; ++j) {
            float y0, y1;
            upk2(acc2[j], y0, y1);
            ylpk[j] = pk2(y0 * invL, y1 * invL);
            float g0 = fmaxf(fabsf(y0) - lamreg[2 * j], 0.f);
            float g1 = fmaxf(fabsf(y1) - lamreg[2 * j + 1], 0.f);
            float z0 = (y0 > 0.f) ? g0 : -g0;
            float z1 = (y1 > 0.f) ? g1 : -g1;
            *(unsigned long long*)&ztr[atom * ZS + mb + 2 * j] = pk2(z0, z1);
        }
    }
    __syncthreads();

    unsigned long long nil2 = pk2(-invL, -invL);

    for (int it = 0; it <= niters; ++it) {
        {
            unsigned long long acc2[4];
#pragma unroll
            for (int q = 0; q < 4; ++q) acc2[q] = 0ULL;
            const float* zp = ztr + m1;
            const ulonglong2* dp = (const ulonglong2*)(d1 + cg * 8);
#pragma unroll 2
            for (int a = 0; a < 256; ++a) {
                float zv = zp[a * ZS];
                unsigned long long vv = pk2(zv, zv);
                ulonglong2 q0 = dp[a * (D1S / 4)];
                ulonglong2 q1 = dp[a * (D1S / 4) + 1];
                ffma2(acc2[0], q0.x, vv);
                ffma2(acc2[1], q0.y, vv);
                ffma2(acc2[2], q1.x, vv);
                ffma2(acc2[3], q1.y, vv);
            }
#pragma unroll
            for (int q = 0; q < 4; ++q) {
                float r0, r1;
                upk2(acc2[q], r0, r1);
                rt[(cg * 8 + 2 * q) * RS + m1] = r0;
                rt[(cg * 8 + 2 * q + 1) * RS + m1] = r1;
            }
        }
        __syncthreads();
        if (it == niters) break;

        {
            unsigned long long acc2[16];
#pragma unroll
            for (int j = 0; j < 16; ++j) acc2[j] = 0ULL;
#pragma unroll 1
            for (int c = 0; c < 64; ++c) {
                float dg = d2[c * 256 + atom];
                unsigned long long dd = pk2(dg, dg);
                const ulonglong2* rp = (const ulonglong2*)(rt + c * RS + mb);
#pragma unroll
                for (int i = 0; i < 8; ++i) {
                    ulonglong2 q = rp[i];
                    ffma2(acc2[2 * i], q.x, dd);
                    ffma2(acc2[2 * i + 1], q.y, dd);
                }
            }
#pragma unroll
            for (int j = 0; j < 16; ++j) {
                unsigned long long zold =
                    *(unsigned long long*)&ztr[atom * ZS + mb + 2 * j];
                unsigned long long w = add2(ylpk[j], zold);
                ffma2(w, acc2[j], nil2);
                float v0, v1;
                upk2(w, v0, v1);
                float g0 = fmaxf(fabsf(v0) - lamreg[2 * j], 0.f);
                float g1 = fmaxf(fabsf(v1) - lamreg[2 * j + 1], 0.f);
                float z0 = (v0 > 0.f) ? g0 : -g0;
                float z1 = (v1 > 0.f) ? g1 : -g1;
                *(unsigned long long*)&ztr[atom * ZS + mb + 2 * j] = pk2(z0, z1);
            }
        }
        __syncthreads();
    }

    size_t zofs = (size_t)b * 256 * 4096 + pl;
    for (int i = t; i < 16384; i += 512) {
        int a = i >> 6, m = i & 63;
        out_z[zofs + (size_t)a * 4096 + m] = ztr[a * ZS + m];
    }
    size_t rofs = (size_t)b * 64 * 4096 + pl;
    for (int i = t; i < 4096; i += 512) {
        int c = i >> 6, m = i & 63;
        out_r[rofs + (size_t)c * 4096 + m] = rt[c * RS + m];
    }
}

__global__ void copy_k(const float* __restrict__ s, float* __restrict__ d, int n) {
    int i = blockIdx.x * blockDim.x + threadIdx.x;
    if (i < n) d[i] = s[i];
}

extern "C" void kernel_launch(void* const* d_in, const int* in_sizes, int n_in,
                              void* d_out, int out_size) {
    const float* x = (const float*)d_in[0];
    const float* conv_w = (const float*)d_in[1];
    const float* conv_b = (const float*)d_in[2];
    const float* r1w1 = (const float*)d_in[3];
    const float* r1w2 = (const float*)d_in[4];
    const float* r2w1 = (const float*)d_in[5];
    const float* r2w2 = (const float*)d_in[6];
    const float* caw1 = (const float*)d_in[7];
    const float* caw2 = (const float*)d_in[8];
    const float* saw = (const float*)d_in[9];
    const float* Dict = (const float*)d_in[10];
    const float* Lp = (const float*)d_in[11];
    const int* nip = (const int*)d_in[12];
    float* out = (float*)d_out;

    float *l, *tb, *avg, *mx, *sca, *s2m, *s2x, *satt, *lam;
    cudaGetSymbolAddress((void**)&l, g_l);
    cudaGetSymbolAddress((void**)&tb, g_t);
    cudaGetSymbolAddress((void**)&avg, g_avg);
    cudaGetSymbolAddress((void**)&mx, g_mx);
    cudaGetSymbolAddress((void**)&sca, g_sca);
    cudaGetSymbolAddress((void**)&s2m, g_s2m);
    cudaGetSymbolAddress((void**)&s2x, g_s2x);
    cudaGetSymbolAddress((void**)&satt, g_satt);
    cudaGetSymbolAddress((void**)&lam, g_lam);

    conv3x3_k<64, 256, false, true><<<dim3(32, 16), 256>>>(x, conv_w, conv_b, l);
    conv3x3_k<256, 128, true, false><<<dim3(32, 8), 256>>>(l, r1w1, nullptr, tb);
    conv1x1_add_k<<<dim3(64, 16), 256>>>(tb, r1w2, l);
    conv3x3_k<256, 128, true, false><<<dim3(32, 8), 256>>>(l, r2w1, nullptr, tb);
    conv1x1_add_k<<<dim3(64, 16), 256>>>(tb, r2w2, l);
    pool_k<<<2048, 256>>>(l, avg, mx);
    camlp_k<<<1, 256>>>(avg, mx, caw1, caw2, sca);
    chan_k<<<64, 256>>>(l, sca, s2m, s2x);
    sconv_k<<<128, 256>>>(s2m, s2x, saw, satt);
    lamT_k<<<dim3(1024, 8), dim3(32, 8)>>>(l, satt, Lp, lam);

    cudaFuncSetAttribute(lista_k, cudaFuncAttributeMaxDynamicSharedMemorySize,
                         LISTA_SMEM);
    lista_k<<<512, 512, LISTA_SMEM>>>(x, Dict, Lp, nip, lam,
                                      out, out + 8 * 256 * 4096);
    copy_k<<<64, 256>>>(Dict, out + 8 * 256 * 4096 + 8 * 64 * 4096, 64 * 256);
}

// round 9
// speedup vs baseline: 1.7261x; 1.0084x over previous
#include <cuda_runtime.h>
#include <cstdint>

__device__ float g_l[8 * 256 * 4096];
__device__ float g_t[8 * 128 * 4096];
__device__ float g_lam[8 * 4096 * 256];
__device__ float g_avg[8 * 256];
__device__ float g_mx[8 * 256];
__device__ float g_sca[8 * 256];
__device__ float g_s2m[8 * 4096];
__device__ float g_s2x[8 * 4096];
__device__ float g_satt[8 * 4096];

__device__ __forceinline__ unsigned long long pk2(float a, float b) {
    unsigned long long r;
    asm("mov.b64 %0, {%1, %2};" : "=l"(r) : "f"(a), "f"(b));
    return r;
}
__device__ __forceinline__ void upk2(unsigned long long v, float& a, float& b) {
    asm("mov.b64 {%0, %1}, %2;" : "=f"(a), "=f"(b) : "l"(v));
}
__device__ __forceinline__ void ffma2(unsigned long long& d, unsigned long long a,
                                      unsigned long long b) {
    asm("fma.rn.f32x2 %0, %1, %2, %0;" : "+l"(d) : "l"(a), "l"(b));
}
__device__ __forceinline__ unsigned long long add2(unsigned long long a,
                                                   unsigned long long b) {
    unsigned long long r;
    asm("add.rn.f32x2 %0, %1, %2;" : "=l"(r) : "l"(a), "l"(b));
    return r;
}

// direct 3x3 conv, pad=1; 128 threads x (2x2 pixels) = 8 rows x 64 cols,
// 8 out-ch per block. grid.x = 8 batch * 8 row-blocks, grid.y = CO/8.
template <int CI, int CO, bool RELU, bool BIAS>
__global__ __launch_bounds__(128) void conv3x3_k(const float* __restrict__ in,
                                                 const float* __restrict__ wt,
                                                 const float* __restrict__ bias,
                                                 float* __restrict__ out) {
    __shared__ __align__(16) float wsh[8 * 64 * 9];  // [ci*9+tap][8 co]
    int tid = threadIdx.x;
    int b = blockIdx.x >> 3, rb = blockIdx.x & 7;
    int w0 = (tid & 31) * 2, h0 = rb * 8 + (tid >> 5) * 2;
    int coBase = blockIdx.y * 8;

    bool rok[4], cok[4];
#pragma unroll
    for (int r = 0; r < 4; ++r) rok[r] = ((unsigned)(h0 - 1 + r) < 64u);
#pragma unroll
    for (int q = 0; q < 4; ++q) cok[q] = ((unsigned)(w0 - 1 + q) < 64u);

    // acc2[p*4 + px]: co pair (2p,2p+1), pixel px = dh*2+dw
    unsigned long long acc2[16];
#pragma unroll
    for (int p = 0; p < 4; ++p) {
        unsigned long long bi =
            BIAS ? pk2(bias[coBase + 2 * p], bias[coBase + 2 * p + 1]) : 0ULL;
#pragma unroll
        for (int px = 0; px < 4; ++px) acc2[p * 4 + px] = bi;
    }

    const float* inb = in + (size_t)b * CI * 4096;
    for (int cc = 0; cc < CI / 64; ++cc) {
        __syncthreads();
        for (int i = tid; i < 8 * 64 * 9; i += 128) {
            int o = i / 576, r = i - o * 576;
            wsh[r * 8 + o] = wt[(size_t)(coBase + o) * (CI * 9) + cc * 576 + r];
        }
        __syncthreads();
        const float* inc = inb + (size_t)cc * 64 * 4096;
#pragma unroll 1
        for (int ci = 0; ci < 64; ++ci) {
            const float* ip = inc + (size_t)ci * 4096;
            float rv[4][4];
#pragma unroll
            for (int r = 0; r < 4; ++r) {
                int rbase = (h0 - 1 + r) * 64 + w0 - 1;
#pragma unroll
                for (int q = 0; q < 4; ++q) {
                    float u = (rok[r] && cok[q]) ? ip[rbase + q] : 0.f;
                    rv[r][q] = RELU ? fmaxf(u, 0.f) : u;
                }
            }
#pragma unroll
            for (int kh = 0; kh < 3; ++kh)
#pragma unroll
                for (int kw = 0; kw < 3; ++kw) {
                    const ulonglong2* wp =
                        (const ulonglong2*)&wsh[(ci * 9 + kh * 3 + kw) * 8];
                    ulonglong2 wq0 = wp[0], wq1 = wp[1];
#pragma unroll
                    for (int dh = 0; dh < 2; ++dh)
#pragma unroll
                        for (int dw = 0; dw < 2; ++dw) {
                            float v = rv[kh + dh][kw + dw];
                            unsigned long long vv = pk2(v, v);
                            int px = dh * 2 + dw;
                            ffma2(acc2[0 * 4 + px], wq0.x, vv);
                            ffma2(acc2[1 * 4 + px], wq0.y, vv);
                            ffma2(acc2[2 * 4 + px], wq1.x, vv);
                            ffma2(acc2[3 * 4 + px], wq1.y, vv);
                        }
                }
        }
    }
    size_t ob = ((size_t)b * CO + coBase) * 4096 + (size_t)h0 * 64 + w0;
#pragma unroll
    for (int p = 0; p < 4; ++p) {
        float a00, b00, a01, b01, a10, b10, a11, b11;
        upk2(acc2[p * 4 + 0], a00, b00);
        upk2(acc2[p * 4 + 1], a01, b01);
        upk2(acc2[p * 4 + 2], a10, b10);
        upk2(acc2[p * 4 + 3], a11, b11);
        float2 r0 = {a00, a01}, r1 = {a10, a11};
        float2 s0 = {b00, b01}, s1 = {b10, b11};
        *(float2*)&out[ob + (size_t)(2 * p) * 4096] = r0;
        *(float2*)&out[ob + (size_t)(2 * p) * 4096 + 64] = r1;
        *(float2*)&out[ob + (size_t)(2 * p + 1) * 4096] = s0;
        *(float2*)&out[ob + (size_t)(2 * p + 1) * 4096 + 64] = s1;
    }
}

// 1x1 conv (relu(t)@w2) + residual add; CI=128, 16 co per block, 2 px/thread
__global__ __launch_bounds__(256) void conv1x1_add_k(const float* __restrict__ tin,
                                                     const float* __restrict__ wt,
                                                     float* __restrict__ lio) {
    __shared__ __align__(16) float wsh[128 * 16];
    int tid = threadIdx.x;
    int p0 = blockIdx.x * 512 + 2 * tid;
    int b = p0 >> 12, hw = p0 & 4095;
    int coBase = blockIdx.y * 16;
    for (int i = tid; i < 2048; i += 256) {
        int o = i >> 7, ci = i & 127;
        wsh[ci * 16 + o] = wt[(size_t)(coBase + o) * 128 + ci];
    }
    __syncthreads();
    unsigned long long acc2[16];
    size_t lb = ((size_t)b * 256 + coBase) * 4096 + hw;
#pragma unroll
    for (int q = 0; q < 8; ++q) {
        float2 v = *(const float2*)&lio[lb + (size_t)(2 * q) * 4096];
        float2 u = *(const float2*)&lio[lb + (size_t)(2 * q + 1) * 4096];
        acc2[2 * q] = pk2(v.x, u.x);
        acc2[2 * q + 1] = pk2(v.y, u.y);
    }
    const float* tb = tin + (size_t)b * 128 * 4096 + hw;
#pragma unroll 1
    for (int ci = 0; ci < 128; ci += 8) {
        float2 v[8];
#pragma unroll
        for (int j = 0; j < 8; ++j) {
            float2 u = *(const float2*)&tb[(size_t)(ci + j) * 4096];
            v[j].x = fmaxf(u.x, 0.f);
            v[j].y = fmaxf(u.y, 0.f);
        }
#pragma unroll
        for (int j = 0; j < 8; ++j) {
            unsigned long long v0 = pk2(v[j].x, v[j].x);
            unsigned long long v1 = pk2(v[j].y, v[j].y);
            const ulonglong2* wp = (const ulonglong2*)&wsh[(ci + j) * 16];
#pragma unroll
            for (int q = 0; q < 4; ++q) {
                ulonglong2 wq = wp[q];
                ffma2(acc2[4 * q], wq.x, v0);
                ffma2(acc2[4 * q + 1], wq.x, v1);
                ffma2(acc2[4 * q + 2], wq.y, v0);
                ffma2(acc2[4 * q + 3], wq.y, v1);
            }
        }
    }
#pragma unroll
    for (int q = 0; q < 8; ++q) {
        float a0, a1, b0_, b1_;
        upk2(acc2[2 * q], a0, b0_);
        upk2(acc2[2 * q + 1], a1, b1_);
        float2 o0 = {a0, a1}, o1 = {b0_, b1_};
        *(float2*)&lio[lb + (size_t)(2 * q) * 4096] = o0;
        *(float2*)&lio[lb + (size_t)(2 * q + 1) * 4096] = o1;
    }
}

__global__ __launch_bounds__(256) void pool_k(const float* __restrict__ l,
                                              float* __restrict__ avg,
                                              float* __restrict__ mx) {
    __shared__ float ss[256], sm[256];
    int bc = blockIdx.x, t = threadIdx.x;
    const float4* p = (const float4*)(l + (size_t)bc * 4096);
    float s = 0.f, m = -3.4e38f;
    for (int i = t; i < 1024; i += 256) {
        float4 v = p[i];
        s += v.x + v.y + v.z + v.w;
        m = fmaxf(m, fmaxf(fmaxf(v.x, v.y), fmaxf(v.z, v.w)));
    }
    ss[t] = s;
    sm[t] = m;
    __syncthreads();
    for (int st = 128; st > 0; st >>= 1) {
        if (t < st) {
            ss[t] += ss[t + st];
            sm[t] = fmaxf(sm[t], sm[t + st]);
        }
        __syncthreads();
    }
    if (t == 0) {
        avg[bc] = ss[0] * (1.f / 4096.f);
        mx[bc] = sm[0];
    }
}

__global__ void camlp_k(const float* __restrict__ avg, const float* __restrict__ mx,
                        const float* __restrict__ w1, const float* __restrict__ w2,
                        float* __restrict__ sca) {
    __shared__ float hsh[128];
    int t = threadIdx.x;
    if (t < 128) {
        int b = t >> 4, j = t & 15;
        float a = 0.f, m = 0.f;
        for (int c = 0; c < 256; ++c) {
            float w = w1[j * 256 + c];
            a += avg[b * 256 + c] * w;
            m += mx[b * 256 + c] * w;
        }
        hsh[b * 16 + j] = fmaxf(a, 0.f) + fmaxf(m, 0.f);
    }
    __syncthreads();
    for (int b = 0; b < 8; ++b) {
        float o = 0.f;
#pragma unroll
        for (int j = 0; j < 16; ++j) o += hsh[b * 16 + j] * w2[t * 16 + j];
        sca[b * 256 + t] = 1.f / (1.f + expf(-o));
    }
}

__global__ __launch_bounds__(256) void chan_k(float* __restrict__ l,
                                              const float* __restrict__ sca,
                                              float* __restrict__ s2m,
                                              float* __restrict__ s2x) {
    int tid = threadIdx.x;
    int p0 = blockIdx.x * 512 + 2 * tid;
    int b = p0 >> 12, hw = p0 & 4095;
    size_t base = (size_t)b * 256 * 4096 + hw;
    float s0 = 0.f, s1 = 0.f, m0 = -3.4e38f, m1 = -3.4e38f;
#pragma unroll 1
    for (int c = 0; c < 256; c += 8) {
        float2 v[8];
#pragma unroll
        for (int j = 0; j < 8; ++j) {
            float2 u = *(float2*)&l[base + (size_t)(c + j) * 4096];
            float sc = sca[b * 256 + c + j];
            v[j].x = u.x * sc;
            v[j].y = u.y * sc;
        }
#pragma unroll
        for (int j = 0; j < 8; ++j) {
            *(float2*)&l[base + (size_t)(c + j) * 4096] = v[j];
            s0 += v[j].x;
            s1 += v[j].y;
            m0 = fmaxf(m0, v[j].x);
            m1 = fmaxf(m1, v[j].y);
        }
    }
    s2m[p0] = s0 * (1.f / 256.f);
    s2m[p0 + 1] = s1 * (1.f / 256.f);
    s2x[p0] = m0;
    s2x[p0 + 1] = m1;
}

__global__ void sconv_k(const float* __restrict__ s2m, const float* __restrict__ s2x,
                        const float* __restrict__ sw, float* __restrict__ satt) {
    int p = blockIdx.x * 256 + threadIdx.x;
    int b = p >> 12, hw = p & 4095, h = hw >> 6, w = hw & 63;
    float a = 0.f;
#pragma unroll
    for (int kh = 0; kh < 3; ++kh) {
        int hh = h + kh - 1;
        if ((unsigned)hh >= 64u) continue;
#pragma unroll
        for (int kw = 0; kw < 3; ++kw) {
            int ww = w + kw - 1;
            if ((unsigned)ww >= 64u) continue;
            int q = b * 4096 + hh * 64 + ww;
            a += s2m[q] * sw[kh * 3 + kw] + s2x[q] * sw[9 + kh * 3 + kw];
        }
    }
    satt[p] = 1.f / (1.f + expf(-a));
}

// lam NHWC = (l * satt) / L, tiled transpose
__global__ void lamT_k(const float* __restrict__ l, const float* __restrict__ satt,
                       const float* __restrict__ Lp, float* __restrict__ lam) {
    __shared__ float tile[32][33];
    int pb = blockIdx.x * 32, cb = blockIdx.y * 32;
    int tx = threadIdx.x, ty = threadIdx.y;
    int b = pb >> 12, pl = pb & 4095;
#pragma unroll
    for (int k = 0; k < 4; ++k) {
        int c = cb + ty + 8 * k;
        tile[ty + 8 * k][tx] = l[((size_t)b * 256 + c) * 4096 + pl + tx];
    }
    __syncthreads();
    float invL = 1.f / Lp[0];
#pragma unroll
    for (int k = 0; k < 4; ++k) {
        int p2 = pb + ty + 8 * k;
        float sc = satt[p2] * invL;
        lam[(size_t)p2 * 256 + cb + tx] = tile[tx][ty + 8 * k] * sc;
    }
}

// ---------------------------------------------------------------------------
// Factorized LISTA: z' = soft(yL + z - (z @ Dict^T) @ Dict / L, lam)
// 64 pixels/CTA, 512 threads; Dict fully SMEM-resident; no S matrix.
// ---------------------------------------------------------------------------
#define ZS 66
#define RS 68
#define D1S 68
#define ZTR_OFF 0
#define RT_OFF 16896
#define D1_OFF (16896 + 4352)
#define D2_OFF (16896 + 4352 + 17408)
#define LISTA_SMEM ((16896 + 4352 + 17408 + 16384) * 4)

__global__ __launch_bounds__(512, 1) void lista_k(
    const float* __restrict__ x, const float* __restrict__ Dict,
    const float* __restrict__ Lp, const int* __restrict__ nip,
    const float* __restrict__ lam_g,
    float* __restrict__ out_z, float* __restrict__ out_r) {
    extern __shared__ __align__(16) float smem[];
    float* ztr = smem + ZTR_OFF;  // [256 a][ZS] z (k-major)
    float* rt = smem + RT_OFF;    // [64 c][RS] r transposed (also x staging)
    float* d1 = smem + D1_OFF;    // [256 a][D1S] Dict[c][a] transposed
    float* d2 = smem + D2_OFF;    // [64 c][256 a] Dict
    int t = threadIdx.x;
    int atom = t & 255, half = t >> 8, mb = half * 32;
    int m1 = t & 63, cg = t >> 6;  // step1 mapping
    int pbase = blockIdx.x * 64;
    int b = pbase >> 12, pl = pbase & 4095;
    float invL = 1.f / Lp[0];
    int niters = nip[0];

    size_t xofs = (size_t)b * 64 * 4096 + pl;
    for (int i = t; i < 4096; i += 512) {
        int c = i >> 6, m = i & 63;
        rt[c * RS + m] = x[xofs + (size_t)c * 4096 + m];
    }
    for (int i = t; i < 16384; i += 512) {
        int c = i >> 8, a = i & 255;
        float d = Dict[i];
        d1[a * D1S + c] = d;
        d2[i] = d;
    }
    __syncthreads();

    float lamreg[32];
    {
        const float* lg = lam_g + ((size_t)(pbase + mb)) * 256 + atom;
#pragma unroll
        for (int m = 0; m < 32; ++m) lamreg[m] = lg[(size_t)m * 256];
    }

    unsigned long long ylpk[16];
    {
        unsigned long long acc2[16];
#pragma unroll
        for (int j = 0; j < 16; ++j) acc2[j] = 0ULL;
#pragma unroll 1
        for (int c = 0; c < 64; ++c) {
            float dg = Dict[c * 256 + atom];
            unsigned long long dd = pk2(dg, dg);
            const ulonglong2* xp = (const ulonglong2*)(rt + c * RS + mb);
#pragma unroll
            for (int i = 0; i < 8; ++i) {
                ulonglong2 q = xp[i];
                ffma2(acc2[2 * i], q.x, dd);
                ffma2(acc2[2 * i + 1], q.y, dd);
            }
        }
#pragma unroll
        for (int j = 0; j < 16; ++j) {
            float y0, y1;
            upk2(acc2[j], y0, y1);
            ylpk[j] = pk2(y0 * invL, y1 * invL);
            float g0 = fmaxf(fabsf(y0) - lamreg[2 * j], 0.f);
            float g1 = fmaxf(fabsf(y1) - lamreg[2 * j + 1], 0.f);
            float z0 = (y0 > 0.f) ? g0 : -g0;
            float z1 = (y1 > 0.f) ? g1 : -g1;
            *(unsigned long long*)&ztr[atom * ZS + mb + 2 * j] = pk2(z0, z1);
        }
    }
    __syncthreads();

    unsigned long long nil2 = pk2(-invL, -invL);

    for (int it = 0; it <= niters; ++it) {
        {
            unsigned long long acc2[4];
#pragma unroll
            for (int q = 0; q < 4; ++q) acc2[q] = 0ULL;
            const float* zp = ztr + m1;
            const ulonglong2* dp = (const ulonglong2*)(d1 + cg * 8);
#pragma unroll 2
            for (int a = 0; a < 256; ++a) {
                float zv = zp[a * ZS];
                unsigned long long vv = pk2(zv, zv);
                ulonglong2 q0 = dp[a * (D1S / 4)];
                ulonglong2 q1 = dp[a * (D1S / 4) + 1];
                ffma2(acc2[0], q0.x, vv);
                ffma2(acc2[1], q0.y, vv);
                ffma2(acc2[2], q1.x, vv);
                ffma2(acc2[3], q1.y, vv);
            }
#pragma unroll
            for (int q = 0; q < 4; ++q) {
                float r0, r1;
                upk2(acc2[q], r0, r1);
                rt[(cg * 8 + 2 * q) * RS + m1] = r0;
                rt[(cg * 8 + 2 * q + 1) * RS + m1] = r1;
            }
        }
        __syncthreads();
        if (it == niters) break;

        {
            unsigned long long acc2[16];
#pragma unroll
            for (int j = 0; j < 16; ++j) acc2[j] = 0ULL;
#pragma unroll 1
            for (int c = 0; c < 64; ++c) {
                float dg = d2[c * 256 + atom];
                unsigned long long dd = pk2(dg, dg);
                const ulonglong2* rp = (const ulonglong2*)(rt + c * RS + mb);
#pragma unroll
                for (int i = 0; i < 8; ++i) {
                    ulonglong2 q = rp[i];
                    ffma2(acc2[2 * i], q.x, dd);
                    ffma2(acc2[2 * i + 1], q.y, dd);
                }
            }
#pragma unroll
            for (int j = 0; j < 16; ++j) {
                unsigned long long zold =
                    *(unsigned long long*)&ztr[atom * ZS + mb + 2 * j];
                unsigned long long w = add2(ylpk[j], zold);
                ffma2(w, acc2[j], nil2);
                float v0, v1;
                upk2(w, v0, v1);
                float g0 = fmaxf(fabsf(v0) - lamreg[2 * j], 0.f);
                float g1 = fmaxf(fabsf(v1) - lamreg[2 * j + 1], 0.f);
                float z0 = (v0 > 0.f) ? g0 : -g0;
                float z1 = (v1 > 0.f) ? g1 : -g1;
                *(unsigned long long*)&ztr[atom * ZS + mb + 2 * j] = pk2(z0, z1);
            }
        }
        __syncthreads();
    }

    size_t zofs = (size_t)b * 256 * 4096 + pl;
    for (int i = t; i < 16384; i += 512) {
        int a = i >> 6, m = i & 63;
        out_z[zofs + (size_t)a * 4096 + m] = ztr[a * ZS + m];
    }
    size_t rofs = (size_t)b * 64 * 4096 + pl;
    for (int i = t; i < 4096; i += 512) {
        int c = i >> 6, m = i & 63;
        out_r[rofs + (size_t)c * 4096 + m] = rt[c * RS + m];
    }
}

__global__ void copy_k(const float* __restrict__ s, float* __restrict__ d, int n) {
    int i = blockIdx.x * blockDim.x + threadIdx.x;
    if (i < n) d[i] = s[i];
}

extern "C" void kernel_launch(void* const* d_in, const int* in_sizes, int n_in,
                              void* d_out, int out_size) {
    const float* x = (const float*)d_in[0];
    const float* conv_w = (const float*)d_in[1];
    const float* conv_b = (const float*)d_in[2];
    const float* r1w1 = (const float*)d_in[3];
    const float* r1w2 = (const float*)d_in[4];
    const float* r2w1 = (const float*)d_in[5];
    const float* r2w2 = (const float*)d_in[6];
    const float* caw1 = (const float*)d_in[7];
    const float* caw2 = (const float*)d_in[8];
    const float* saw = (const float*)d_in[9];
    const float* Dict = (const float*)d_in[10];
    const float* Lp = (const float*)d_in[11];
    const int* nip = (const int*)d_in[12];
    float* out = (float*)d_out;

    float *l, *tb, *avg, *mx, *sca, *s2m, *s2x, *satt, *lam;
    cudaGetSymbolAddress((void**)&l, g_l);
    cudaGetSymbolAddress((void**)&tb, g_t);
    cudaGetSymbolAddress((void**)&avg, g_avg);
    cudaGetSymbolAddress((void**)&mx, g_mx);
    cudaGetSymbolAddress((void**)&sca, g_sca);
    cudaGetSymbolAddress((void**)&s2m, g_s2m);
    cudaGetSymbolAddress((void**)&s2x, g_s2x);
    cudaGetSymbolAddress((void**)&satt, g_satt);
    cudaGetSymbolAddress((void**)&lam, g_lam);

    conv3x3_k<64, 256, false, true><<<dim3(64, 32), 128>>>(x, conv_w, conv_b, l);
    conv3x3_k<256, 128, true, false><<<dim3(64, 16), 128>>>(l, r1w1, nullptr, tb);
    conv1x1_add_k<<<dim3(64, 16), 256>>>(tb, r1w2, l);
    conv3x3_k<256, 128, true, false><<<dim3(64, 16), 128>>>(l, r2w1, nullptr, tb);
    conv1x1_add_k<<<dim3(64, 16), 256>>>(tb, r2w2, l);
    pool_k<<<2048, 256>>>(l, avg, mx);
    camlp_k<<<1, 256>>>(avg, mx, caw1, caw2, sca);
    chan_k<<<64, 256>>>(l, sca, s2m, s2x);
    sconv_k<<<128, 256>>>(s2m, s2x, saw, satt);
    lamT_k<<<dim3(1024, 8), dim3(32, 8)>>>(l, satt, Lp, lam);

    cudaFuncSetAttribute(lista_k, cudaFuncAttributeMaxDynamicSharedMemorySize,
                         LISTA_SMEM);
    lista_k<<<512, 512, LISTA_SMEM>>>(x, Dict, Lp, nip, lam,
                                      out, out + 8 * 256 * 4096);
    copy_k<<<64, 256>>>(Dict, out + 8 * 256 * 4096 + 8 * 64 * 4096, 64 * 256);
}

// round 10
// speedup vs baseline: 2.7555x; 1.5963x over previous
#include <cuda_runtime.h>
#include <cuda_bf16.h>
#include <cstdint>

__device__ float g_l[8 * 256 * 4096];
__device__ float g_t[8 * 128 * 4096];
__device__ float g_lam[8 * 4096 * 256];
__device__ float g_avg[8 * 256];
__device__ float g_mx[8 * 256];
__device__ float g_sca[8 * 256];
__device__ float g_s2m[8 * 4096];
__device__ float g_s2x[8 * 4096];
__device__ float g_satt[8 * 4096];

__device__ __forceinline__ unsigned long long pk2(float a, float b) {
    unsigned long long r;
    asm("mov.b64 %0, {%1, %2};" : "=l"(r) : "f"(a), "f"(b));
    return r;
}
__device__ __forceinline__ void upk2(unsigned long long v, float& a, float& b) {
    asm("mov.b64 {%0, %1}, %2;" : "=f"(a), "=f"(b) : "l"(v));
}
__device__ __forceinline__ void ffma2(unsigned long long& d, unsigned long long a,
                                      unsigned long long b) {
    asm("fma.rn.f32x2 %0, %1, %2, %0;" : "+l"(d) : "l"(a), "l"(b));
}

// ---------------- conv kernels (unchanged from R9) ----------------
template <int CI, int CO, bool RELU, bool BIAS>
__global__ __launch_bounds__(128) void conv3x3_k(const float* __restrict__ in,
                                                 const float* __restrict__ wt,
                                                 const float* __restrict__ bias,
                                                 float* __restrict__ out) {
    __shared__ __align__(16) float wsh[8 * 64 * 9];
    int tid = threadIdx.x;
    int b = blockIdx.x >> 3, rb = blockIdx.x & 7;
    int w0 = (tid & 31) * 2, h0 = rb * 8 + (tid >> 5) * 2;
    int coBase = blockIdx.y * 8;

    bool rok[4], cok[4];
#pragma unroll
    for (int r = 0; r < 4; ++r) rok[r] = ((unsigned)(h0 - 1 + r) < 64u);
#pragma unroll
    for (int q = 0; q < 4; ++q) cok[q] = ((unsigned)(w0 - 1 + q) < 64u);

    unsigned long long acc2[16];
#pragma unroll
    for (int p = 0; p < 4; ++p) {
        unsigned long long bi =
            BIAS ? pk2(bias[coBase + 2 * p], bias[coBase + 2 * p + 1]) : 0ULL;
#pragma unroll
        for (int px = 0; px < 4; ++px) acc2[p * 4 + px] = bi;
    }

    const float* inb = in + (size_t)b * CI * 4096;
    for (int cc = 0; cc < CI / 64; ++cc) {
        __syncthreads();
        for (int i = tid; i < 8 * 64 * 9; i += 128) {
            int o = i / 576, r = i - o * 576;
            wsh[r * 8 + o] = wt[(size_t)(coBase + o) * (CI * 9) + cc * 576 + r];
        }
        __syncthreads();
        const float* inc = inb + (size_t)cc * 64 * 4096;
#pragma unroll 1
        for (int ci = 0; ci < 64; ++ci) {
            const float* ip = inc + (size_t)ci * 4096;
            float rv[4][4];
#pragma unroll
            for (int r = 0; r < 4; ++r) {
                int rbase = (h0 - 1 + r) * 64 + w0 - 1;
#pragma unroll
                for (int q = 0; q < 4; ++q) {
                    float u = (rok[r] && cok[q]) ? ip[rbase + q] : 0.f;
                    rv[r][q] = RELU ? fmaxf(u, 0.f) : u;
                }
            }
#pragma unroll
            for (int kh = 0; kh < 3; ++kh)
#pragma unroll
                for (int kw = 0; kw < 3; ++kw) {
                    const ulonglong2* wp =
                        (const ulonglong2*)&wsh[(ci * 9 + kh * 3 + kw) * 8];
                    ulonglong2 wq0 = wp[0], wq1 = wp[1];
#pragma unroll
                    for (int dh = 0; dh < 2; ++dh)
#pragma unroll
                        for (int dw = 0; dw < 2; ++dw) {
                            float v = rv[kh + dh][kw + dw];
                            unsigned long long vv = pk2(v, v);
                            int px = dh * 2 + dw;
                            ffma2(acc2[0 * 4 + px], wq0.x, vv);
                            ffma2(acc2[1 * 4 + px], wq0.y, vv);
                            ffma2(acc2[2 * 4 + px], wq1.x, vv);
                            ffma2(acc2[3 * 4 + px], wq1.y, vv);
                        }
                }
        }
    }
    size_t ob = ((size_t)b * CO + coBase) * 4096 + (size_t)h0 * 64 + w0;
#pragma unroll
    for (int p = 0; p < 4; ++p) {
        float a00, b00, a01, b01, a10, b10, a11, b11;
        upk2(acc2[p * 4 + 0], a00, b00);
        upk2(acc2[p * 4 + 1], a01, b01);
        upk2(acc2[p * 4 + 2], a10, b10);
        upk2(acc2[p * 4 + 3], a11, b11);
        float2 r0 = {a00, a01}, r1 = {a10, a11};
        float2 s0 = {b00, b01}, s1 = {b10, b11};
        *(float2*)&out[ob + (size_t)(2 * p) * 4096] = r0;
        *(float2*)&out[ob + (size_t)(2 * p) * 4096 + 64] = r1;
        *(float2*)&out[ob + (size_t)(2 * p + 1) * 4096] = s0;
        *(float2*)&out[ob + (size_t)(2 * p + 1) * 4096 + 64] = s1;
    }
}

__global__ __launch_bounds__(256) void conv1x1_add_k(const float* __restrict__ tin,
                                                     const float* __restrict__ wt,
                                                     float* __restrict__ lio) {
    __shared__ __align__(16) float wsh[128 * 16];
    int tid = threadIdx.x;
    int p0 = blockIdx.x * 512 + 2 * tid;
    int b = p0 >> 12, hw = p0 & 4095;
    int coBase = blockIdx.y * 16;
    for (int i = tid; i < 2048; i += 256) {
        int o = i >> 7, ci = i & 127;
        wsh[ci * 16 + o] = wt[(size_t)(coBase + o) * 128 + ci];
    }
    __syncthreads();
    unsigned long long acc2[16];
    size_t lb = ((size_t)b * 256 + coBase) * 4096 + hw;
#pragma unroll
    for (int q = 0; q < 8; ++q) {
        float2 v = *(const float2*)&lio[lb + (size_t)(2 * q) * 4096];
        float2 u = *(const float2*)&lio[lb + (size_t)(2 * q + 1) * 4096];
        acc2[2 * q] = pk2(v.x, u.x);
        acc2[2 * q + 1] = pk2(v.y, u.y);
    }
    const float* tb = tin + (size_t)b * 128 * 4096 + hw;
#pragma unroll 1
    for (int ci = 0; ci < 128; ci += 8) {
        float2 v[8];
#pragma unroll
        for (int j = 0; j < 8; ++j) {
            float2 u = *(const float2*)&tb[(size_t)(ci + j) * 4096];
            v[j].x = fmaxf(u.x, 0.f);
            v[j].y = fmaxf(u.y, 0.f);
        }
#pragma unroll
        for (int j = 0; j < 8; ++j) {
            unsigned long long v0 = pk2(v[j].x, v[j].x);
            unsigned long long v1 = pk2(v[j].y, v[j].y);
            const ulonglong2* wp = (const ulonglong2*)&wsh[(ci + j) * 16];
#pragma unroll
            for (int q = 0; q < 4; ++q) {
                ulonglong2 wq = wp[q];
                ffma2(acc2[4 * q], wq.x, v0);
                ffma2(acc2[4 * q + 1], wq.x, v1);
                ffma2(acc2[4 * q + 2], wq.y, v0);
                ffma2(acc2[4 * q + 3], wq.y, v1);
            }
        }
    }
#pragma unroll
    for (int q = 0; q < 8; ++q) {
        float a0, a1, b0_, b1_;
        upk2(acc2[2 * q], a0, b0_);
        upk2(acc2[2 * q + 1], a1, b1_);
        float2 o0 = {a0, a1}, o1 = {b0_, b1_};
        *(float2*)&lio[lb + (size_t)(2 * q) * 4096] = o0;
        *(float2*)&lio[lb + (size_t)(2 * q + 1) * 4096] = o1;
    }
}

__global__ __launch_bounds__(256) void pool_k(const float* __restrict__ l,
                                              float* __restrict__ avg,
                                              float* __restrict__ mx) {
    __shared__ float ss[256], sm[256];
    int bc = blockIdx.x, t = threadIdx.x;
    const float4* p = (const float4*)(l + (size_t)bc * 4096);
    float s = 0.f, m = -3.4e38f;
    for (int i = t; i < 1024; i += 256) {
        float4 v = p[i];
        s += v.x + v.y + v.z + v.w;
        m = fmaxf(m, fmaxf(fmaxf(v.x, v.y), fmaxf(v.z, v.w)));
    }
    ss[t] = s;
    sm[t] = m;
    __syncthreads();
    for (int st = 128; st > 0; st >>= 1) {
        if (t < st) {
            ss[t] += ss[t + st];
            sm[t] = fmaxf(sm[t], sm[t + st]);
        }
        __syncthreads();
    }
    if (t == 0) {
        avg[bc] = ss[0] * (1.f / 4096.f);
        mx[bc] = sm[0];
    }
}

__global__ void camlp_k(const float* __restrict__ avg, const float* __restrict__ mx,
                        const float* __restrict__ w1, const float* __restrict__ w2,
                        float* __restrict__ sca) {
    __shared__ float hsh[128];
    int t = threadIdx.x;
    if (t < 128) {
        int b = t >> 4, j = t & 15;
        float a = 0.f, m = 0.f;
        for (int c = 0; c < 256; ++c) {
            float w = w1[j * 256 + c];
            a += avg[b * 256 + c] * w;
            m += mx[b * 256 + c] * w;
        }
        hsh[b * 16 + j] = fmaxf(a, 0.f) + fmaxf(m, 0.f);
    }
    __syncthreads();
    for (int b = 0; b < 8; ++b) {
        float o = 0.f;
#pragma unroll
        for (int j = 0; j < 16; ++j) o += hsh[b * 16 + j] * w2[t * 16 + j];
        sca[b * 256 + t] = 1.f / (1.f + expf(-o));
    }
}

__global__ __launch_bounds__(256) void chan_k(float* __restrict__ l,
                                              const float* __restrict__ sca,
                                              float* __restrict__ s2m,
                                              float* __restrict__ s2x) {
    int tid = threadIdx.x;
    int p0 = blockIdx.x * 512 + 2 * tid;
    int b = p0 >> 12, hw = p0 & 4095;
    size_t base = (size_t)b * 256 * 4096 + hw;
    float s0 = 0.f, s1 = 0.f, m0 = -3.4e38f, m1 = -3.4e38f;
#pragma unroll 1
    for (int c = 0; c < 256; c += 8) {
        float2 v[8];
#pragma unroll
        for (int j = 0; j < 8; ++j) {
            float2 u = *(float2*)&l[base + (size_t)(c + j) * 4096];
            float sc = sca[b * 256 + c + j];
            v[j].x = u.x * sc;
            v[j].y = u.y * sc;
        }
#pragma unroll
        for (int j = 0; j < 8; ++j) {
            *(float2*)&l[base + (size_t)(c + j) * 4096] = v[j];
            s0 += v[j].x;
            s1 += v[j].y;
            m0 = fmaxf(m0, v[j].x);
            m1 = fmaxf(m1, v[j].y);
        }
    }
    s2m[p0] = s0 * (1.f / 256.f);
    s2m[p0 + 1] = s1 * (1.f / 256.f);
    s2x[p0] = m0;
    s2x[p0 + 1] = m1;
}

__global__ void sconv_k(const float* __restrict__ s2m, const float* __restrict__ s2x,
                        const float* __restrict__ sw, float* __restrict__ satt) {
    int p = blockIdx.x * 256 + threadIdx.x;
    int b = p >> 12, hw = p & 4095, h = hw >> 6, w = hw & 63;
    float a = 0.f;
#pragma unroll
    for (int kh = 0; kh < 3; ++kh) {
        int hh = h + kh - 1;
        if ((unsigned)hh >= 64u) continue;
#pragma unroll
        for (int kw = 0; kw < 3; ++kw) {
            int ww = w + kw - 1;
            if ((unsigned)ww >= 64u) continue;
            int q = b * 4096 + hh * 64 + ww;
            a += s2m[q] * sw[kh * 3 + kw] + s2x[q] * sw[9 + kh * 3 + kw];
        }
    }
    satt[p] = 1.f / (1.f + expf(-a));
}

__global__ void lamT_k(const float* __restrict__ l, const float* __restrict__ satt,
                       const float* __restrict__ Lp, float* __restrict__ lam) {
    __shared__ float tile[32][33];
    int pb = blockIdx.x * 32, cb = blockIdx.y * 32;
    int tx = threadIdx.x, ty = threadIdx.y;
    int b = pb >> 12, pl = pb & 4095;
#pragma unroll
    for (int k = 0; k < 4; ++k) {
        int c = cb + ty + 8 * k;
        tile[ty + 8 * k][tx] = l[((size_t)b * 256 + c) * 4096 + pl + tx];
    }
    __syncthreads();
    float invL = 1.f / Lp[0];
#pragma unroll
    for (int k = 0; k < 4; ++k) {
        int p2 = pb + ty + 8 * k;
        float sc = satt[p2] * invL;
        lam[(size_t)p2 * 256 + cb + tx] = tile[tx][ty + 8 * k] * sc;
    }
}

// ---------------------------------------------------------------------------
// LISTA via mma.sync bf16 (hi/lo split), residual form:
//   e = x - z@Dict^T ; z' = soft(z + (e@Dict)/L, lam); x_recon = final z@Dict^T
// 64 px/CTA, 256 threads (8 warps), 1 CTA/SM.
// ---------------------------------------------------------------------------
#define ZH_OFF 0
#define ZL_OFF 33792
#define EH_OFF 67584
#define EL_OFF 76800
#define DH_OFF 86016
#define DL_OFF 119808
#define LAM_OFF 153600
#define LISTA_SMEM 220416
#define LDZ 264
#define LDE 72
#define LDD 264
#define LDL 261

__device__ __forceinline__ float b2f(unsigned u) {
    return __uint_as_float(u << 16);
}
__device__ __forceinline__ unsigned short f2b(float f) {
    __nv_bfloat16 h = __float2bfloat16(f);
    return *(unsigned short*)&h;
}
__device__ __forceinline__ void ldsm4(unsigned r[4], unsigned addr) {
    asm volatile("ldmatrix.sync.aligned.m8n8.x4.shared.b16 {%0,%1,%2,%3}, [%4];"
                 : "=r"(r[0]), "=r"(r[1]), "=r"(r[2]), "=r"(r[3])
                 : "r"(addr));
}
__device__ __forceinline__ void mma16816(float d[4], const unsigned a[4],
                                         unsigned b0, unsigned b1) {
    asm volatile(
        "mma.sync.aligned.m16n8k16.row.col.f32.bf16.bf16.f32 "
        "{%0,%1,%2,%3},{%4,%5,%6,%7},{%8,%9},{%0,%1,%2,%3};"
        : "+f"(d[0]), "+f"(d[1]), "+f"(d[2]), "+f"(d[3])
        : "r"(a[0]), "r"(a[1]), "r"(a[2]), "r"(a[3]), "r"(b0), "r"(b1));
}

// step1: R[64m x 64c] = Z(split) @ Dict^T ; warp w: m-block w&3, c cols (w>>2)*32
__device__ __forceinline__ void run_step1(float R[16], unsigned zhA, unsigned zlA,
                                          unsigned dhA, unsigned dlA, int mB1,
                                          int cB1, int lane) {
#pragma unroll
    for (int i = 0; i < 16; ++i) R[i] = 0.f;
    int arow = mB1 * 16 + (lane & 15);
    int acolg = (lane >> 4) << 3;
    int brow0 = cB1 + (lane & 7) + (((lane >> 4) & 1) << 3);
    int bcolg = (((lane >> 3) & 1) << 3);
#pragma unroll 2
    for (int ks = 0; ks < 16; ++ks) {
        int k0 = ks * 16;
        unsigned ah[4], al[4], bh0[4], bh1[4], bl0[4], bl1[4];
        unsigned aoff = (unsigned)((arow * LDZ + k0 + acolg) * 2);
        ldsm4(ah, zhA + aoff);
        ldsm4(al, zlA + aoff);
        unsigned boff0 = (unsigned)((brow0 * LDD + k0 + bcolg) * 2);
        unsigned boff1 = (unsigned)(((brow0 + 16) * LDD + k0 + bcolg) * 2);
        ldsm4(bh0, dhA + boff0);
        ldsm4(bl0, dlA + boff0);
        ldsm4(bh1, dhA + boff1);
        ldsm4(bl1, dlA + boff1);
        // tiles: nb=0: {bh0[0],bh0[1]} (c..+8), {bh0[2],bh0[3]} (c+8..16); nb=1 same +16
        mma16816(&R[0], ah, bh0[0], bh0[1]);
        mma16816(&R[0], ah, bl0[0], bl0[1]);
        mma16816(&R[0], al, bh0[0], bh0[1]);
        mma16816(&R[4], ah, bh0[2], bh0[3]);
        mma16816(&R[4], ah, bl0[2], bl0[3]);
        mma16816(&R[4], al, bh0[2], bh0[3]);
        mma16816(&R[8], ah, bh1[0], bh1[1]);
        mma16816(&R[8], ah, bl1[0], bl1[1]);
        mma16816(&R[8], al, bh1[0], bh1[1]);
        mma16816(&R[12], ah, bh1[2], bh1[3]);
        mma16816(&R[12], ah, bl1[2], bl1[3]);
        mma16816(&R[12], al, bh1[2], bh1[3]);
    }
}

// step2: Q[64m x 256a] = E(split) @ Dict ; warp w: m 2 blocks (w&1)*32, a (w>>1)*64
__device__ __forceinline__ void run_step2(float q[64], unsigned ehA, unsigned elA,
                                          const unsigned short* dh,
                                          const unsigned short* dl, int mB2,
                                          int aB2, int lane) {
#pragma unroll
    for (int i = 0; i < 64; ++i) q[i] = 0.f;
    int arow = mB2 * 32 + (lane & 15);
    int acolg = (lane >> 4) << 3;
    int acol_b = aB2 + (lane >> 2);
    int kr_b = (lane & 3) << 1;
#pragma unroll
    for (int ks = 0; ks < 4; ++ks) {
        int k0 = ks * 16;
        unsigned ah0[4], al0[4], ah1[4], al1[4];
        unsigned aoff0 = (unsigned)((arow * LDE + k0 + acolg) * 2);
        unsigned aoff1 = (unsigned)(((arow + 16) * LDE + k0 + acolg) * 2);
        ldsm4(ah0, ehA + aoff0);
        ldsm4(al0, elA + aoff0);
        ldsm4(ah1, ehA + aoff1);
        ldsm4(al1, elA + aoff1);
        int kr = k0 + kr_b;
#pragma unroll
        for (int nt = 0; nt < 8; ++nt) {
            int ac = acol_b + nt * 8;
            unsigned h0 = (unsigned)dh[kr * LDD + ac] |
                          ((unsigned)dh[(kr + 1) * LDD + ac] << 16);
            unsigned h1 = (unsigned)dh[(kr + 8) * LDD + ac] |
                          ((unsigned)dh[(kr + 9) * LDD + ac] << 16);
            unsigned l0 = (unsigned)dl[kr * LDD + ac] |
                          ((unsigned)dl[(kr + 1) * LDD + ac] << 16);
            unsigned l1 = (unsigned)dl[(kr + 8) * LDD + ac] |
                          ((unsigned)dl[(kr + 9) * LDD + ac] << 16);
            mma16816(&q[nt * 4], ah0, h0, h1);
            mma16816(&q[nt * 4], ah0, l0, l1);
            mma16816(&q[nt * 4], al0, h0, h1);
            mma16816(&q[32 + nt * 4], ah1, h0, h1);
            mma16816(&q[32 + nt * 4], ah1, l0, l1);
            mma16816(&q[32 + nt * 4], al1, h0, h1);
        }
    }
}

__global__ __launch_bounds__(256, 1) void lista_mma_k(
    const float* __restrict__ x, const float* __restrict__ Dict,
    const float* __restrict__ Lp, const int* __restrict__ nip,
    const float* __restrict__ lam_g, float* __restrict__ out_z,
    float* __restrict__ out_r) {
    extern __shared__ __align__(16) char smem[];
    unsigned short* zh = (unsigned short*)(smem + ZH_OFF);
    unsigned short* zl = (unsigned short*)(smem + ZL_OFF);
    unsigned short* eh = (unsigned short*)(smem + EH_OFF);
    unsigned short* el = (unsigned short*)(smem + EL_OFF);
    unsigned short* dh = (unsigned short*)(smem + DH_OFF);
    unsigned short* dl = (unsigned short*)(smem + DL_OFF);
    float* lam = (float*)(smem + LAM_OFF);
    float* xrec = (float*)(smem + EH_OFF);  // overlay after last step1
    float* zfp = lam;                       // overlay on last z-epilogue

    int t = threadIdx.x, w = t >> 5, lane = t & 31;
    int mB1 = w & 3, cB1 = (w >> 2) * 32;
    int mB2 = w & 1, aB2 = (w >> 1) * 64;
    int pbase = blockIdx.x * 64;
    int b = pbase >> 12, pl = pbase & 4095;
    float invL = 1.f / Lp[0];
    int niters = nip[0];

    unsigned zhA = (unsigned)__cvta_generic_to_shared(zh);
    unsigned zlA = (unsigned)__cvta_generic_to_shared(zl);
    unsigned ehA = (unsigned)__cvta_generic_to_shared(eh);
    unsigned elA = (unsigned)__cvta_generic_to_shared(el);
    unsigned dhA = (unsigned)__cvta_generic_to_shared(dh);
    unsigned dlA = (unsigned)__cvta_generic_to_shared(dl);

    // stage lam
    for (int i = t; i < 16384; i += 256) {
        int m = i >> 8, a = i & 255;
        lam[m * LDL + a] = lam_g[(size_t)(pbase + m) * 256 + a];
    }
    // stage Dict hi/lo [c][a]
    for (int i = t; i < 16384; i += 256) {
        int c = i >> 8, a = i & 255;
        float v = Dict[i];
        unsigned short h = f2b(v);
        dh[c * LDD + a] = h;
        dl[c * LDD + a] = f2b(v - b2f(h));
    }
    // stage x (split) into e as A operand [m][c]
    size_t xofs = (size_t)b * 64 * 4096 + pl;
    for (int i = t; i < 4096; i += 256) {
        int c = i >> 6, m = i & 63;
        float v = x[xofs + (size_t)c * 4096 + m];
        unsigned short h = f2b(v);
        eh[m * LDE + c] = h;
        el[m * LDE + c] = f2b(v - b2f(h));
    }
    __syncthreads();

    // xfrag: x values at this thread's step1 fragment positions
    float xfrag[16];
    {
        int r0 = mB1 * 16 + (lane >> 2);
#pragma unroll
        for (int nt = 0; nt < 4; ++nt) {
            int c2 = cB1 + nt * 8 + ((lane & 3) << 1);
            xfrag[nt * 4 + 0] = x[((size_t)b * 64 + c2) * 4096 + pl + r0];
            xfrag[nt * 4 + 1] = x[((size_t)b * 64 + c2 + 1) * 4096 + pl + r0];
            xfrag[nt * 4 + 2] = x[((size_t)b * 64 + c2) * 4096 + pl + r0 + 8];
            xfrag[nt * 4 + 3] = x[((size_t)b * 64 + c2 + 1) * 4096 + pl + r0 + 8];
        }
    }

    // ---- init: y = x @ Dict (step2 with e=x); z0 = soft(y, lam)
    {
        float q[64];
        run_step2(q, ehA, elA, dh, dl, mB2, aB2, lane);
        bool wz = (niters == 0);
#pragma unroll
        for (int blk = 0; blk < 2; ++blk)
#pragma unroll
            for (int nt = 0; nt < 8; ++nt) {
                int r = mB2 * 32 + blk * 16 + (lane >> 2);
                int a2 = aB2 + nt * 8 + ((lane & 3) << 1);
                const float* qq = &q[blk * 32 + nt * 4];
#pragma unroll
                for (int rr = 0; rr < 2; ++rr) {
                    int row = r + rr * 8;
                    float y0 = qq[rr * 2], y1 = qq[rr * 2 + 1];
                    float l0 = lam[row * LDL + a2], l1 = lam[row * LDL + a2 + 1];
                    float g0 = fmaxf(fabsf(y0) - l0, 0.f);
                    float g1 = fmaxf(fabsf(y1) - l1, 0.f);
                    float z0 = (y0 > 0.f) ? g0 : -g0;
                    float z1 = (y1 > 0.f) ? g1 : -g1;
                    unsigned short h0 = f2b(z0), h1 = f2b(z1);
                    *(unsigned*)&zh[row * LDZ + a2] =
                        (unsigned)h0 | ((unsigned)h1 << 16);
                    *(unsigned*)&zl[row * LDZ + a2] =
                        (unsigned)f2b(z0 - b2f(h0)) |
                        ((unsigned)f2b(z1 - b2f(h1)) << 16);
                    if (wz) {
                        zfp[row * LDL + a2] = z0;
                        zfp[row * LDL + a2 + 1] = z1;
                    }
                }
            }
    }
    __syncthreads();

    // ---- iterations
    for (int it = 0; it < niters; ++it) {
        float R[16];
        run_step1(R, zhA, zlA, dhA, dlA, mB1, cB1, lane);
        // e = x - R  (write split)
        {
            int r0 = mB1 * 16 + (lane >> 2);
#pragma unroll
            for (int nt = 0; nt < 4; ++nt) {
                int c2 = cB1 + nt * 8 + ((lane & 3) << 1);
#pragma unroll
                for (int rr = 0; rr < 2; ++rr) {
                    int row = r0 + rr * 8;
                    float e0 = xfrag[nt * 4 + rr * 2] - R[nt * 4 + rr * 2];
                    float e1 = xfrag[nt * 4 + rr * 2 + 1] - R[nt * 4 + rr * 2 + 1];
                    unsigned short h0 = f2b(e0), h1 = f2b(e1);
                    *(unsigned*)&eh[row * LDE + c2] =
                        (unsigned)h0 | ((unsigned)h1 << 16);
                    *(unsigned*)&el[row * LDE + c2] =
                        (unsigned)f2b(e0 - b2f(h0)) |
                        ((unsigned)f2b(e1 - b2f(h1)) << 16);
                }
            }
        }
        __syncthreads();
        float q[64];
        run_step2(q, ehA, elA, dh, dl, mB2, aB2, lane);
        bool wz = (it == niters - 1);
#pragma unroll
        for (int blk = 0; blk < 2; ++blk)
#pragma unroll
            for (int nt = 0; nt < 8; ++nt) {
                int r = mB2 * 32 + blk * 16 + (lane >> 2);
                int a2 = aB2 + nt * 8 + ((lane & 3) << 1);
                const float* qq = &q[blk * 32 + nt * 4];
#pragma unroll
                for (int rr = 0; rr < 2; ++rr) {
                    int row = r + rr * 8;
                    unsigned hz = *(unsigned*)&zh[row * LDZ + a2];
                    unsigned lz = *(unsigned*)&zl[row * LDZ + a2];
                    float zo0 = b2f(hz & 0xffffu) + b2f(lz & 0xffffu);
                    float zo1 = b2f(hz >> 16) + b2f(lz >> 16);
                    float w0 = zo0 + qq[rr * 2] * invL;
                    float w1 = zo1 + qq[rr * 2 + 1] * invL;
                    float l0 = lam[row * LDL + a2], l1 = lam[row * LDL + a2 + 1];
                    float g0 = fmaxf(fabsf(w0) - l0, 0.f);
                    float g1 = fmaxf(fabsf(w1) - l1, 0.f);
                    float z0 = (w0 > 0.f) ? g0 : -g0;
                    float z1 = (w1 > 0.f) ? g1 : -g1;
                    unsigned short h0 = f2b(z0), h1 = f2b(z1);
                    *(unsigned*)&zh[row * LDZ + a2] =
                        (unsigned)h0 | ((unsigned)h1 << 16);
                    *(unsigned*)&zl[row * LDZ + a2] =
                        (unsigned)f2b(z0 - b2f(h0)) |
                        ((unsigned)f2b(z1 - b2f(h1)) << 16);
                    if (wz) {
                        zfp[row * LDL + a2] = z0;
                        zfp[row * LDL + a2 + 1] = z1;
                    }
                }
            }
        __syncthreads();
    }

    // ---- final recon: x_recon = z @ Dict^T
    {
        float R[16];
        run_step1(R, zhA, zlA, dhA, dlA, mB1, cB1, lane);
        __syncthreads();  // all reads of e-region done before overlay write
        int r0 = mB1 * 16 + (lane >> 2);
#pragma unroll
        for (int nt = 0; nt < 4; ++nt) {
            int c2 = cB1 + nt * 8 + ((lane & 3) << 1);
            xrec[r0 * 65 + c2] = R[nt * 4 + 0];
            xrec[r0 * 65 + c2 + 1] = R[nt * 4 + 1];
            xrec[(r0 + 8) * 65 + c2] = R[nt * 4 + 2];
            xrec[(r0 + 8) * 65 + c2 + 1] = R[nt * 4 + 3];
        }
    }
    __syncthreads();

    size_t zofs = (size_t)b * 256 * 4096 + pl;
    for (int i = t; i < 16384; i += 256) {
        int a = i >> 6, m = i & 63;
        out_z[zofs + (size_t)a * 4096 + m] = zfp[m * LDL + a];
    }
    size_t rofs = (size_t)b * 64 * 4096 + pl;
    for (int i = t; i < 4096; i += 256) {
        int c = i >> 6, m = i & 63;
        out_r[rofs + (size_t)c * 4096 + m] = xrec[m * 65 + c];
    }
}

__global__ void copy_k(const float* __restrict__ s, float* __restrict__ d, int n) {
    int i = blockIdx.x * blockDim.x + threadIdx.x;
    if (i < n) d[i] = s[i];
}

extern "C" void kernel_launch(void* const* d_in, const int* in_sizes, int n_in,
                              void* d_out, int out_size) {
    const float* x = (const float*)d_in[0];
    const float* conv_w = (const float*)d_in[1];
    const float* conv_b = (const float*)d_in[2];
    const float* r1w1 = (const float*)d_in[3];
    const float* r1w2 = (const float*)d_in[4];
    const float* r2w1 = (const float*)d_in[5];
    const float* r2w2 = (const float*)d_in[6];
    const float* caw1 = (const float*)d_in[7];
    const float* caw2 = (const float*)d_in[8];
    const float* saw = (const float*)d_in[9];
    const float* Dict = (const float*)d_in[10];
    const float* Lp = (const float*)d_in[11];
    const int* nip = (const int*)d_in[12];
    float* out = (float*)d_out;

    float *l, *tb, *avg, *mx, *sca, *s2m, *s2x, *satt, *lam;
    cudaGetSymbolAddress((void**)&l, g_l);
    cudaGetSymbolAddress((void**)&tb, g_t);
    cudaGetSymbolAddress((void**)&avg, g_avg);
    cudaGetSymbolAddress((void**)&mx, g_mx);
    cudaGetSymbolAddress((void**)&sca, g_sca);
    cudaGetSymbolAddress((void**)&s2m, g_s2m);
    cudaGetSymbolAddress((void**)&s2x, g_s2x);
    cudaGetSymbolAddress((void**)&satt, g_satt);
    cudaGetSymbolAddress((void**)&lam, g_lam);

    conv3x3_k<64, 256, false, true><<<dim3(64, 32), 128>>>(x, conv_w, conv_b, l);
    conv3x3_k<256, 128, true, false><<<dim3(64, 16), 128>>>(l, r1w1, nullptr, tb);
    conv1x1_add_k<<<dim3(64, 16), 256>>>(tb, r1w2, l);
    conv3x3_k<256, 128, true, false><<<dim3(64, 16), 128>>>(l, r2w1, nullptr, tb);
    conv1x1_add_k<<<dim3(64, 16), 256>>>(tb, r2w2, l);
    pool_k<<<2048, 256>>>(l, avg, mx);
    camlp_k<<<1, 256>>>(avg, mx, caw1, caw2, sca);
    chan_k<<<64, 256>>>(l, sca, s2m, s2x);
    sconv_k<<<128, 256>>>(s2m, s2x, saw, satt);
    lamT_k<<<dim3(1024, 8), dim3(32, 8)>>>(l, satt, Lp, lam);

    cudaFuncSetAttribute(lista_mma_k, cudaFuncAttributeMaxDynamicSharedMemorySize,
                         LISTA_SMEM);
    lista_mma_k<<<512, 256, LISTA_SMEM>>>(x, Dict, Lp, nip, lam,
                                          out, out + 8 * 256 * 4096);
    copy_k<<<64, 256>>>(Dict, out + 8 * 256 * 4096 + 8 * 64 * 4096, 64 * 256);
}